// round 11
// baseline (speedup 1.0000x reference)
#include <cuda_runtime.h>
#include <cuda_bf16.h>
#include <cuda_fp16.h>

#define NN   50000
#define EE   800000
#define ETOT 850000      // EE + NN self loops
#define INC  128
#define HH   8
#define HC   256
#define OUTC 40
#define NEG  0.2f
#define SCAN_BLK 1024
#define NBLK ((NN + SCAN_BLK - 1) / SCAN_BLK)   // 49
#define NSPLIT 25088                             // node/row split (multiple of 128 and 2)

// ---------------- scratch (device globals; no allocation) ----------------
__device__ __nv_bfloat162 g_h1b[NN * HC / 2];   // layer-1 features (bf16 pairs)
__device__ float  g_asrc1[NN * HH];
__device__ float  g_adst1[NN * HH];
__device__ __half2 g_out1h[NN * HC / 2];        // relu(out1+b1) (fp16 pairs) = layer-2 input
__device__ __half2 g_g2h[NN * OUTC / 2];        // layer-2 features (fp16 pairs)
__device__ float  g_as2[NN];
__device__ float  g_ad2[NN];
__device__ int    g_deg[NN];                    // REAL edges only (self loop added in scan)
__device__ int    g_bagg[NBLK];                 // published block aggregates (+1), 0 = not ready
__device__ int    g_rowptr[NN + 1];
__device__ int    g_cursor[NN];
__device__ int    g_csr_src[ETOT];

__device__ __forceinline__ float lrelu(float x) { return x > 0.f ? x : NEG * x; }

__device__ __forceinline__ void mma_tf32(float* c, const unsigned* a, const unsigned* b) {
    asm("mma.sync.aligned.m16n8k8.row.col.f32.tf32.tf32.f32 "
        "{%0,%1,%2,%3},{%4,%5,%6,%7},{%8,%9},{%0,%1,%2,%3};"
        : "+f"(c[0]), "+f"(c[1]), "+f"(c[2]), "+f"(c[3])
        : "r"(a[0]), "r"(a[1]), "r"(a[2]), "r"(a[3]), "r"(b[0]), "r"(b[1]));
}

__device__ __forceinline__ void mma_f16(float* c, const unsigned* a, const unsigned* b) {
    asm("mma.sync.aligned.m16n8k16.row.col.f32.f16.f16.f32 "
        "{%0,%1,%2,%3},{%4,%5,%6,%7},{%8,%9},{%0,%1,%2,%3};"
        : "+f"(c[0]), "+f"(c[1]), "+f"(c[2]), "+f"(c[3])
        : "r"(a[0]), "r"(a[1]), "r"(a[2]), "r"(a[3]), "r"(b[0]), "r"(b[1]));
}

#define CP_ASYNC16(sa, ga) asm volatile("cp.async.cg.shared.global [%0],[%1],16;\n" :: "r"(sa), "l"(ga))
#define CP_COMMIT()  asm volatile("cp.async.commit_group;\n" ::: "memory")
#define CP_WAIT1()   asm volatile("cp.async.wait_group 1;\n" ::: "memory")
#define CP_WAIT0()   asm volatile("cp.async.wait_group 0;\n" ::: "memory")

// ---------------- CSR build ----------------
__global__ void k_hist(const int* __restrict__ ei) {
    int t = blockIdx.x * blockDim.x + threadIdx.x;
    if (t * 4 >= EE) return;
    int4 d = *(const int4*)&ei[EE + t * 4];
    atomicAdd(&g_deg[d.x], 1);
    atomicAdd(&g_deg[d.y], 1);
    atomicAdd(&g_deg[d.z], 1);
    atomicAdd(&g_deg[d.w], 1);
}

// single-kernel exclusive scan with decoupled lookback (49 blocks, all resident)
__global__ void k_scan_f() {
    __shared__ int wsum[32];
    __shared__ int sbase;
    int t = threadIdx.x, b = blockIdx.x;
    int lane = t & 31, wid = t >> 5;
    int i = b * SCAN_BLK + t;
    int v = (i < NN) ? g_deg[i] + 1 : 0;      // +1 self loop
    int sc = v;
#pragma unroll
    for (int off = 1; off < 32; off <<= 1) {
        int u = __shfl_up_sync(0xffffffffu, sc, off);
        if (lane >= off) sc += u;
    }
    if (lane == 31) wsum[wid] = sc;
    __syncthreads();
    if (t < 32) {
        int u = wsum[t];
#pragma unroll
        for (int off = 1; off < 32; off <<= 1) {
            int uu = __shfl_up_sync(0xffffffffu, u, off);
            if (t >= off) u += uu;
        }
        wsum[t] = u;
        if (t == 31) atomicExch(&g_bagg[b], u + 1);   // publish total (+1 flag)
    }
    __syncthreads();
    if (t < 32) {
        int base = 0;
        for (int j = lane; j < b; j += 32) {
            int a;
            do { a = atomicAdd(&g_bagg[j], 0); } while (a == 0);
            base += a - 1;
        }
#pragma unroll
        for (int m = 16; m >= 1; m >>= 1) base += __shfl_xor_sync(0xffffffffu, base, m);
        if (t == 0) sbase = base;
    }
    __syncthreads();
    int warpoff = (wid > 0) ? wsum[wid - 1] : 0;
    if (i < NN) {
        int pos = sbase + warpoff + sc - v;    // exclusive
        g_rowptr[i] = pos;
        g_cursor[i] = pos;
    }
    if (b == 0 && t == 0) g_rowptr[NN] = ETOT;
}

__global__ void k_scatter(const int* __restrict__ ei) {
    int e = blockIdx.x * blockDim.x + threadIdx.x;
    if (e < ETOT) {
        int src, dst;
        if (e < EE) { src = ei[e]; dst = ei[EE + e]; }
        else        { src = e - EE; dst = src; }
        int pos = atomicAdd(&g_cursor[dst], 1);
        g_csr_src[pos] = src;
    }
    if (e < NN) g_deg[e] = 0;     // re-zero for next call (deterministic)
    if (e < NBLK) g_bagg[e] = 0;  // re-arm lookback flags
}

// ---------------- GEMM1 (tf32 TC, cp.async double-buffered) + fused att coeffs
__global__ void k_gemm1_tc(const float* __restrict__ A, const float* __restrict__ B,
                           const float* __restrict__ as1, const float* __restrict__ ad1) {
    __shared__ float As[2][128][20];
    __shared__ float Bs[2][16][132];
    int tid = threadIdx.x;
    int wid = tid >> 5, lane = tid & 31;
    int warpM = wid & 3, warpN = wid >> 2;
    int g = lane >> 2, tig = lane & 3;
    int bm = blockIdx.x * 128, bn = blockIdx.y * 128;

    float acc[2][8][4] = {};

    int ar = tid >> 2, ac = (tid & 3) * 4;
    int arow0 = bm + ar;       if (arow0 > NN - 1) arow0 = NN - 1;
    int arow1 = bm + ar + 64;  if (arow1 > NN - 1) arow1 = NN - 1;
    int br = tid >> 5, bc = (tid & 31) * 4;

    for (int it = 0; it < 9; it++) {
        if (it < 8) {
            int k0 = it * 16, buf = it & 1;
            CP_ASYNC16((unsigned)__cvta_generic_to_shared(&As[buf][ar][ac]),      &A[arow0 * INC + k0 + ac]);
            CP_ASYNC16((unsigned)__cvta_generic_to_shared(&As[buf][ar + 64][ac]), &A[arow1 * INC + k0 + ac]);
            CP_ASYNC16((unsigned)__cvta_generic_to_shared(&Bs[buf][br][bc]),      &B[(k0 + br) * HC + bn + bc]);
            CP_ASYNC16((unsigned)__cvta_generic_to_shared(&Bs[buf][br + 8][bc]),  &B[(k0 + br + 8) * HC + bn + bc]);
            CP_COMMIT();
        }
        if (it == 0) continue;
        if (it < 8) CP_WAIT1(); else CP_WAIT0();
        __syncthreads();
        int cb = (it - 1) & 1;
#pragma unroll
        for (int kk = 0; kk < 16; kk += 8) {
            unsigned a[2][4];
#pragma unroll
            for (int mi = 0; mi < 2; mi++) {
                int mrow = warpM * 32 + mi * 16;
                a[mi][0] = __float_as_uint(As[cb][mrow + g][kk + tig]);
                a[mi][1] = __float_as_uint(As[cb][mrow + g + 8][kk + tig]);
                a[mi][2] = __float_as_uint(As[cb][mrow + g][kk + tig + 4]);
                a[mi][3] = __float_as_uint(As[cb][mrow + g + 8][kk + tig + 4]);
            }
            unsigned b[8][2];
#pragma unroll
            for (int ni = 0; ni < 8; ni++) {
                int nc = warpN * 64 + ni * 8 + g;
                b[ni][0] = __float_as_uint(Bs[cb][kk + tig][nc]);
                b[ni][1] = __float_as_uint(Bs[cb][kk + tig + 4][nc]);
            }
#pragma unroll
            for (int mi = 0; mi < 2; mi++)
#pragma unroll
                for (int ni = 0; ni < 8; ni++)
                    mma_tf32(acc[mi][ni], a[mi], b[ni]);
        }
        __syncthreads();
    }

    float ps[2][2][2] = {}, pd[2][2][2] = {};
#pragma unroll
    for (int mi = 0; mi < 2; mi++) {
        int row0 = bm + warpM * 32 + mi * 16 + g;
        int row1 = row0 + 8;
#pragma unroll
        for (int ni = 0; ni < 8; ni++) {
            int col = bn + warpN * 64 + ni * 8 + tig * 2;
            int hh = ni >> 2;
            float s0 = __ldg(&as1[col]), s1 = __ldg(&as1[col + 1]);
            float d0 = __ldg(&ad1[col]), d1 = __ldg(&ad1[col + 1]);
            float c0 = acc[mi][ni][0], c1 = acc[mi][ni][1];
            float c2 = acc[mi][ni][2], c3 = acc[mi][ni][3];
            ps[mi][0][hh] += c0 * s0 + c1 * s1;
            ps[mi][1][hh] += c2 * s0 + c3 * s1;
            pd[mi][0][hh] += c0 * d0 + c1 * d1;
            pd[mi][1][hh] += c2 * d0 + c3 * d1;
            if (row0 < NN) g_h1b[(row0 * HC + col) >> 1] = __floats2bfloat162_rn(c0, c1);
            if (row1 < NN) g_h1b[(row1 * HC + col) >> 1] = __floats2bfloat162_rn(c2, c3);
        }
    }
#pragma unroll
    for (int mi = 0; mi < 2; mi++)
#pragma unroll
        for (int rh = 0; rh < 2; rh++)
#pragma unroll
            for (int hh = 0; hh < 2; hh++) {
                float vs = ps[mi][rh][hh], vd = pd[mi][rh][hh];
                vs += __shfl_xor_sync(0xffffffffu, vs, 1);
                vs += __shfl_xor_sync(0xffffffffu, vs, 2);
                vd += __shfl_xor_sync(0xffffffffu, vd, 1);
                vd += __shfl_xor_sync(0xffffffffu, vd, 2);
                if (tig == 0) {
                    int row = bm + warpM * 32 + mi * 16 + g + rh * 8;
                    int head = ((bn + warpN * 64) >> 5) + hh;
                    if (row < NN) {
                        g_asrc1[row * HH + head] = vs;
                        g_adst1[row * HH + head] = vd;
                    }
                }
            }
}

// ---------------- layer-1: single-pass agg + fused bias/relu store -----------
// 16 edges per iteration (4 independent LDG.128 in flight per warp).
__global__ void k_l1agg(int nbase, const float* __restrict__ b1v) {
    int tid = threadIdx.x;
    int node = nbase + blockIdx.x * 2 + (tid >> 7);
    int w = (tid >> 5) & 3, lane = tid & 31;
    int row = g_rowptr[node], end = g_rowptr[node + 1];
    int q = lane >> 3, cr = lane & 7;
    float dh = g_adst1[node * HH + cr];          // head = cr for exp phase
    int hsel = 2 * w + (cr >> 2);                // head of this lane's channels
    int ub = w * 32 + cr * 4;                    // bf16x2 unit base within row
    float acc[8] = {};
    float psum = 0.f;
    for (int k = row; k < end; k += 16) {
        int  ii[4]; bool ee[4]; int ss[4]; float pp[4];
#pragma unroll
        for (int j = 0; j < 4; j++) {
            ii[j] = k + 4 * j + q;
            ee[j] = ii[j] < end;
            ss[j] = g_csr_src[ee[j] ? ii[j] : end - 1];
        }
#pragma unroll
        for (int j = 0; j < 4; j++) {
            pp[j] = ee[j] ? __expf(lrelu(__ldg(&g_asrc1[ss[j] * HH + cr]) + dh)) : 0.f;
            psum += pp[j];
        }
        uint4 uu[4];
#pragma unroll
        for (int j = 0; j < 4; j++) {
            uu[j] = make_uint4(0u, 0u, 0u, 0u);
            if (ee[j]) uu[j] = __ldg((const uint4*)&g_h1b[ss[j] * (HC / 2) + ub]);
        }
#pragma unroll
        for (int j = 0; j < 4; j++) {
            float wj = __shfl_sync(0xffffffffu, pp[j], (q << 3) + hsel);
            float2 f0 = __bfloat1622float2(*reinterpret_cast<__nv_bfloat162*>(&uu[j].x));
            float2 f1 = __bfloat1622float2(*reinterpret_cast<__nv_bfloat162*>(&uu[j].y));
            float2 f2 = __bfloat1622float2(*reinterpret_cast<__nv_bfloat162*>(&uu[j].z));
            float2 f3 = __bfloat1622float2(*reinterpret_cast<__nv_bfloat162*>(&uu[j].w));
            acc[0] += wj * f0.x; acc[1] += wj * f0.y;
            acc[2] += wj * f1.x; acc[3] += wj * f1.y;
            acc[4] += wj * f2.x; acc[5] += wj * f2.y;
            acc[6] += wj * f3.x; acc[7] += wj * f3.y;
        }
    }
#pragma unroll
    for (int i = 0; i < 8; i++) {
        acc[i] += __shfl_xor_sync(0xffffffffu, acc[i], 8);
        acc[i] += __shfl_xor_sync(0xffffffffu, acc[i], 16);
    }
    psum += __shfl_xor_sync(0xffffffffu, psum, 8);
    psum += __shfl_xor_sync(0xffffffffu, psum, 16);
    float inv = 1.f / __shfl_sync(0xffffffffu, psum, hsel);
    if (lane < 8) {
        int cb = ub * 2;                          // float channel base
        float4 bA = *(const float4*)&b1v[cb];
        float4 bB = *(const float4*)&b1v[cb + 4];
        __half2 h0 = __floats2half2_rn(fmaxf(acc[0] * inv + bA.x, 0.f), fmaxf(acc[1] * inv + bA.y, 0.f));
        __half2 h1 = __floats2half2_rn(fmaxf(acc[2] * inv + bA.z, 0.f), fmaxf(acc[3] * inv + bA.w, 0.f));
        __half2 h2 = __floats2half2_rn(fmaxf(acc[4] * inv + bB.x, 0.f), fmaxf(acc[5] * inv + bB.y, 0.f));
        __half2 h3 = __floats2half2_rn(fmaxf(acc[6] * inv + bB.z, 0.f), fmaxf(acc[7] * inv + bB.w, 0.f));
        uint4 st = make_uint4(*(unsigned*)&h0, *(unsigned*)&h1,
                              *(unsigned*)&h2, *(unsigned*)&h3);
        *(uint4*)&g_out1h[node * (HC / 2) + ub] = st;
    }
}

// ---------------- GEMM2 (fp16 TC, cp.async 2-stage): g2 = out1 @ W2 ----------
__global__ void k_gemm2_tc(int mbase, const float* __restrict__ W2,
                           const float* __restrict__ as2v, const float* __restrict__ ad2v) {
    __shared__ unsigned Ah[2][128][20];   // half2; 16 used + 4 pad
    __shared__ unsigned Bp[2][16][40];    // half2 packed along k
    int tid = threadIdx.x;
    int wid = tid >> 5, lane = tid & 31;
    int g = lane >> 2, tig = lane & 3;
    int bm = mbase + blockIdx.x * 128;

    float acc[5][4] = {};

    int ar = tid >> 1, ac4 = (tid & 1) * 2;
    int arow = bm + ar; if (arow > NN - 1) arow = NN - 1;

    for (int it = 0; it < 9; it++) {
        if (it < 8) {
            int k0 = it * 32, buf = it & 1;
            CP_ASYNC16((unsigned)__cvta_generic_to_shared(&Ah[buf][ar][ac4 * 4]),
                       &g_out1h[arow * (HC / 2) + (k0 >> 1) + ac4 * 4]);
            CP_ASYNC16((unsigned)__cvta_generic_to_shared(&Ah[buf][ar][(ac4 + 1) * 4]),
                       &g_out1h[arow * (HC / 2) + (k0 >> 1) + (ac4 + 1) * 4]);
            CP_COMMIT();
            for (int idx = tid; idx < 640; idx += 256) {
                int k2 = idx / 40, n = idx - k2 * 40;
                float f0 = W2[(k0 + 2 * k2) * OUTC + n];
                float f1 = W2[(k0 + 2 * k2 + 1) * OUTC + n];
                __half2 hp = __floats2half2_rn(f0, f1);
                Bp[buf][k2][n] = *(unsigned*)&hp;
            }
        }
        if (it == 0) continue;
        if (it < 8) CP_WAIT1(); else CP_WAIT0();
        __syncthreads();
        int cb = (it - 1) & 1;
        int mrow = wid * 16;
#pragma unroll
        for (int s = 0; s < 2; s++) {
            unsigned a[4];
            a[0] = Ah[cb][mrow + g][8 * s + tig];
            a[1] = Ah[cb][mrow + g + 8][8 * s + tig];
            a[2] = Ah[cb][mrow + g][8 * s + tig + 4];
            a[3] = Ah[cb][mrow + g + 8][8 * s + tig + 4];
#pragma unroll
            for (int ni = 0; ni < 5; ni++) {
                unsigned b[2];
                int nc = ni * 8 + g;
                b[0] = Bp[cb][8 * s + tig][nc];
                b[1] = Bp[cb][8 * s + tig + 4][nc];
                mma_f16(acc[ni], a, b);
            }
        }
        __syncthreads();
    }

    int row0 = bm + wid * 16 + g;
    int row1 = row0 + 8;
    float ps0 = 0.f, ps1 = 0.f, pd0 = 0.f, pd1 = 0.f;
#pragma unroll
    for (int ni = 0; ni < 5; ni++) {
        int col = ni * 8 + tig * 2;
        float s0 = __ldg(&as2v[col]), s1 = __ldg(&as2v[col + 1]);
        float d0 = __ldg(&ad2v[col]), d1 = __ldg(&ad2v[col + 1]);
        float c0 = acc[ni][0], c1 = acc[ni][1], c2 = acc[ni][2], c3 = acc[ni][3];
        ps0 += c0 * s0 + c1 * s1;
        ps1 += c2 * s0 + c3 * s1;
        pd0 += c0 * d0 + c1 * d1;
        pd1 += c2 * d0 + c3 * d1;
        if (row0 < NN) g_g2h[row0 * (OUTC / 2) + (col >> 1)] = __floats2half2_rn(c0, c1);
        if (row1 < NN) g_g2h[row1 * (OUTC / 2) + (col >> 1)] = __floats2half2_rn(c2, c3);
    }
    ps0 += __shfl_xor_sync(0xffffffffu, ps0, 1); ps0 += __shfl_xor_sync(0xffffffffu, ps0, 2);
    ps1 += __shfl_xor_sync(0xffffffffu, ps1, 1); ps1 += __shfl_xor_sync(0xffffffffu, ps1, 2);
    pd0 += __shfl_xor_sync(0xffffffffu, pd0, 1); pd0 += __shfl_xor_sync(0xffffffffu, pd0, 2);
    pd1 += __shfl_xor_sync(0xffffffffu, pd1, 1); pd1 += __shfl_xor_sync(0xffffffffu, pd1, 2);
    if (tig == 0) {
        if (row0 < NN) { g_as2[row0] = ps0; g_ad2[row0] = pd0; }
        if (row1 < NN) { g_as2[row1] = ps1; g_ad2[row1] = pd1; }
    }
}

// ---------------- layer-2: single-pass agg + bias + log_softmax --------------
__global__ void k_l2agg(float* __restrict__ dout, const float* __restrict__ b2) {
    int node = (blockIdx.x * blockDim.x + threadIdx.x) >> 5;
    int lane = threadIdx.x & 31;
    if (node >= NN) return;
    int row = g_rowptr[node], end = g_rowptr[node + 1];
    float adi = g_ad2[node];
    float a0 = 0.f, a1 = 0.f, psum = 0.f;
    for (int k = row; k < end; k += 32) {
        int idx = k + lane;
        int sl = g_csr_src[idx < end ? idx : end - 1];
        float p = (idx < end) ? __expf(lrelu(__ldg(&g_as2[sl]) + adi)) : 0.f;
        psum += p;
        int cnt = end - k; if (cnt > 32) cnt = 32;
        for (int e0 = 0; e0 < cnt; e0 += 8) {
#pragma unroll
            for (int e2 = 0; e2 < 8; e2++) {
                int e = e0 + e2;
                int s = __shfl_sync(0xffffffffu, sl, e);
                float al = __shfl_sync(0xffffffffu, p, e);
                unsigned u = 0;
                if (e < cnt && lane < 20) u = __ldg((const unsigned*)&g_g2h[s * (OUTC / 2) + lane]);
                __half2 hv = *reinterpret_cast<__half2*>(&u);
                float2 f = __half22float2(hv);
                a0 += al * f.x;
                a1 += al * f.y;
            }
        }
    }
#pragma unroll
    for (int m = 16; m >= 1; m >>= 1) psum += __shfl_xor_sync(0xffffffffu, psum, m);
    float inv = 1.f / psum;
    float v0 = -3.4e38f, v1 = -3.4e38f;
    if (lane < 20) {
        v0 = a0 * inv + b2[2 * lane];
        v1 = a1 * inv + b2[2 * lane + 1];
    }
    float mx = fmaxf(v0, v1);
#pragma unroll
    for (int m = 16; m >= 1; m >>= 1)
        mx = fmaxf(mx, __shfl_xor_sync(0xffffffffu, mx, m));
    float sum = (lane < 20) ? (expf(v0 - mx) + expf(v1 - mx)) : 0.f;
#pragma unroll
    for (int m = 16; m >= 1; m >>= 1)
        sum += __shfl_xor_sync(0xffffffffu, sum, m);
    float ls = logf(sum);
    if (lane < 20)
        *(float2*)&dout[node * OUTC + 2 * lane] = make_float2(v0 - mx - ls, v1 - mx - ls);
}

// ---------------- launch: forked CSR/gemm1, pipelined l1agg/gemm2 ------------
extern "C" void kernel_launch(void* const* d_in, const int* in_sizes, int n_in,
                              void* d_out, int out_size) {
    const float* x   = (const float*)d_in[0];
    const int*   ei  = (const int*)d_in[1];
    const float* W1  = (const float*)d_in[2];
    const float* as1 = (const float*)d_in[3];
    const float* ad1 = (const float*)d_in[4];
    const float* b1  = (const float*)d_in[5];
    const float* W2  = (const float*)d_in[6];
    const float* as2 = (const float*)d_in[7];
    const float* ad2 = (const float*)d_in[8];
    const float* b2  = (const float*)d_in[9];
    float* out = (float*)d_out;

    static cudaStream_t s1 = 0;
    static cudaEvent_t evF = 0, evJ = 0, evA = 0, evB = 0, evG = 0;
    if (s1 == 0) {
        cudaStreamCreateWithFlags(&s1, cudaStreamNonBlocking);
        cudaEventCreateWithFlags(&evF, cudaEventDisableTiming);
        cudaEventCreateWithFlags(&evJ, cudaEventDisableTiming);
        cudaEventCreateWithFlags(&evA, cudaEventDisableTiming);
        cudaEventCreateWithFlags(&evB, cudaEventDisableTiming);
        cudaEventCreateWithFlags(&evG, cudaEventDisableTiming);
    }

    // fork: gemm1 (reads x/W1 only) parallel to CSR build
    cudaEventRecord(evF, (cudaStream_t)0);
    cudaStreamWaitEvent(s1, evF, 0);
    k_gemm1_tc<<<dim3((NN + 127) / 128, HC / 128), 256, 0, s1>>>(x, W1, as1, ad1);
    cudaEventRecord(evJ, s1);

    // CSR build on the main stream
    k_hist<<<(EE / 4 + 255) / 256, 256>>>(ei);
    k_scan_f<<<NBLK, SCAN_BLK>>>();
    k_scatter<<<(ETOT + 255) / 256, 256>>>(ei);

    // join, then pipelined l1agg / gemm2 (gemm2 is row-local)
    cudaStreamWaitEvent((cudaStream_t)0, evJ, 0);
    k_l1agg<<<NSPLIT / 2, 256>>>(0, b1);
    cudaEventRecord(evA, (cudaStream_t)0);
    k_l1agg<<<(NN - NSPLIT) / 2, 256>>>(NSPLIT, b1);
    cudaEventRecord(evB, (cudaStream_t)0);

    cudaStreamWaitEvent(s1, evA, 0);
    k_gemm2_tc<<<NSPLIT / 128, 256, 0, s1>>>(0, W2, as2, ad2);
    cudaStreamWaitEvent(s1, evB, 0);
    k_gemm2_tc<<<(NN - NSPLIT + 127) / 128, 256, 0, s1>>>(NSPLIT, W2, as2, ad2);
    cudaEventRecord(evG, s1);

    cudaStreamWaitEvent((cudaStream_t)0, evG, 0);
    k_l2agg<<<(NN + 7) / 8, 256>>>(out, b2);
}

// round 12
// speedup vs baseline: 1.0863x; 1.0863x over previous
#include <cuda_runtime.h>
#include <cuda_bf16.h>
#include <cuda_fp16.h>

#define NN   50000
#define EE   800000
#define ETOT 850000      // EE + NN self loops
#define INC  128
#define HH   8
#define HC   256
#define OUTC 40
#define NEG  0.2f
#define SCAN_BLK 1024
#define NBLK ((NN + SCAN_BLK - 1) / SCAN_BLK)   // 49

// ---------------- scratch (device globals; no allocation) ----------------
__device__ __nv_bfloat162 g_h1b[NN * HC / 2];   // layer-1 features (bf16 pairs)
__device__ float  g_asrc1[NN * HH];
__device__ float  g_adst1[NN * HH];
__device__ __half2 g_out1h[NN * HC / 2];        // relu(out1+b1) (fp16 pairs) = layer-2 input
__device__ __half2 g_g2h[NN * OUTC / 2];        // layer-2 features (fp16 pairs)
__device__ float  g_as2[NN];
__device__ float  g_ad2[NN];
__device__ int    g_deg[NN];                    // REAL edges only (self loop added in scan)
__device__ int    g_bagg[NBLK];                 // published block aggregates (+1), 0 = not ready
__device__ int    g_rowptr[NN + 1];
__device__ int    g_cursor[NN];
__device__ int    g_csr_src[ETOT];

__device__ __forceinline__ float lrelu(float x) { return x > 0.f ? x : NEG * x; }

__device__ __forceinline__ void mma_tf32(float* c, const unsigned* a, const unsigned* b) {
    asm("mma.sync.aligned.m16n8k8.row.col.f32.tf32.tf32.f32 "
        "{%0,%1,%2,%3},{%4,%5,%6,%7},{%8,%9},{%0,%1,%2,%3};"
        : "+f"(c[0]), "+f"(c[1]), "+f"(c[2]), "+f"(c[3])
        : "r"(a[0]), "r"(a[1]), "r"(a[2]), "r"(a[3]), "r"(b[0]), "r"(b[1]));
}

__device__ __forceinline__ void mma_f16(float* c, const unsigned* a, const unsigned* b) {
    asm("mma.sync.aligned.m16n8k16.row.col.f32.f16.f16.f32 "
        "{%0,%1,%2,%3},{%4,%5,%6,%7},{%8,%9},{%0,%1,%2,%3};"
        : "+f"(c[0]), "+f"(c[1]), "+f"(c[2]), "+f"(c[3])
        : "r"(a[0]), "r"(a[1]), "r"(a[2]), "r"(a[3]), "r"(b[0]), "r"(b[1]));
}

#define CP_ASYNC16(sa, ga) asm volatile("cp.async.cg.shared.global [%0],[%1],16;\n" :: "r"(sa), "l"(ga))
#define CP_COMMIT()  asm volatile("cp.async.commit_group;\n" ::: "memory")
#define CP_WAIT1()   asm volatile("cp.async.wait_group 1;\n" ::: "memory")
#define CP_WAIT0()   asm volatile("cp.async.wait_group 0;\n" ::: "memory")

// ---------------- CSR build ----------------
__global__ void k_hist(const int* __restrict__ ei) {
    int t = blockIdx.x * blockDim.x + threadIdx.x;
    if (t * 4 >= EE) return;
    int4 d = *(const int4*)&ei[EE + t * 4];
    atomicAdd(&g_deg[d.x], 1);
    atomicAdd(&g_deg[d.y], 1);
    atomicAdd(&g_deg[d.z], 1);
    atomicAdd(&g_deg[d.w], 1);
}

// single-kernel exclusive scan with decoupled lookback (49 blocks, all resident)
__global__ void k_scan_f() {
    __shared__ int wsum[32];
    __shared__ int sbase;
    int t = threadIdx.x, b = blockIdx.x;
    int lane = t & 31, wid = t >> 5;
    int i = b * SCAN_BLK + t;
    int v = (i < NN) ? g_deg[i] + 1 : 0;      // +1 self loop
    int sc = v;
#pragma unroll
    for (int off = 1; off < 32; off <<= 1) {
        int u = __shfl_up_sync(0xffffffffu, sc, off);
        if (lane >= off) sc += u;
    }
    if (lane == 31) wsum[wid] = sc;
    __syncthreads();
    if (t < 32) {
        int u = wsum[t];
#pragma unroll
        for (int off = 1; off < 32; off <<= 1) {
            int uu = __shfl_up_sync(0xffffffffu, u, off);
            if (t >= off) u += uu;
        }
        wsum[t] = u;
        if (t == 31) atomicExch(&g_bagg[b], u + 1);   // publish total (+1 flag)
    }
    __syncthreads();
    if (t < 32) {
        int base = 0;
        for (int j = lane; j < b; j += 32) {
            int a;
            do { a = atomicAdd(&g_bagg[j], 0); } while (a == 0);
            base += a - 1;
        }
#pragma unroll
        for (int m = 16; m >= 1; m >>= 1) base += __shfl_xor_sync(0xffffffffu, base, m);
        if (t == 0) sbase = base;
    }
    __syncthreads();
    int warpoff = (wid > 0) ? wsum[wid - 1] : 0;
    if (i < NN) {
        int pos = sbase + warpoff + sc - v;    // exclusive
        g_rowptr[i] = pos;
        g_cursor[i] = pos;
    }
    if (b == 0 && t == 0) g_rowptr[NN] = ETOT;
}

__global__ void k_scatter(const int* __restrict__ ei) {
    int e = blockIdx.x * blockDim.x + threadIdx.x;
    if (e < ETOT) {
        int src, dst;
        if (e < EE) { src = ei[e]; dst = ei[EE + e]; }
        else        { src = e - EE; dst = src; }
        int pos = atomicAdd(&g_cursor[dst], 1);
        g_csr_src[pos] = src;
    }
    if (e < NN) g_deg[e] = 0;     // re-zero for next call (deterministic)
    if (e < NBLK) g_bagg[e] = 0;  // re-arm lookback flags
}

// ---------------- GEMM1 (tf32 TC, cp.async double-buffered) + fused att coeffs
__global__ void k_gemm1_tc(const float* __restrict__ A, const float* __restrict__ B,
                           const float* __restrict__ as1, const float* __restrict__ ad1) {
    __shared__ float As[2][128][20];
    __shared__ float Bs[2][16][132];
    int tid = threadIdx.x;
    int wid = tid >> 5, lane = tid & 31;
    int warpM = wid & 3, warpN = wid >> 2;
    int g = lane >> 2, tig = lane & 3;
    int bm = blockIdx.x * 128, bn = blockIdx.y * 128;

    float acc[2][8][4] = {};

    int ar = tid >> 2, ac = (tid & 3) * 4;
    int arow0 = bm + ar;       if (arow0 > NN - 1) arow0 = NN - 1;
    int arow1 = bm + ar + 64;  if (arow1 > NN - 1) arow1 = NN - 1;
    int br = tid >> 5, bc = (tid & 31) * 4;

    for (int it = 0; it < 9; it++) {
        if (it < 8) {
            int k0 = it * 16, buf = it & 1;
            CP_ASYNC16((unsigned)__cvta_generic_to_shared(&As[buf][ar][ac]),      &A[arow0 * INC + k0 + ac]);
            CP_ASYNC16((unsigned)__cvta_generic_to_shared(&As[buf][ar + 64][ac]), &A[arow1 * INC + k0 + ac]);
            CP_ASYNC16((unsigned)__cvta_generic_to_shared(&Bs[buf][br][bc]),      &B[(k0 + br) * HC + bn + bc]);
            CP_ASYNC16((unsigned)__cvta_generic_to_shared(&Bs[buf][br + 8][bc]),  &B[(k0 + br + 8) * HC + bn + bc]);
            CP_COMMIT();
        }
        if (it == 0) continue;
        if (it < 8) CP_WAIT1(); else CP_WAIT0();
        __syncthreads();
        int cb = (it - 1) & 1;
#pragma unroll
        for (int kk = 0; kk < 16; kk += 8) {
            unsigned a[2][4];
#pragma unroll
            for (int mi = 0; mi < 2; mi++) {
                int mrow = warpM * 32 + mi * 16;
                a[mi][0] = __float_as_uint(As[cb][mrow + g][kk + tig]);
                a[mi][1] = __float_as_uint(As[cb][mrow + g + 8][kk + tig]);
                a[mi][2] = __float_as_uint(As[cb][mrow + g][kk + tig + 4]);
                a[mi][3] = __float_as_uint(As[cb][mrow + g + 8][kk + tig + 4]);
            }
            unsigned b[8][2];
#pragma unroll
            for (int ni = 0; ni < 8; ni++) {
                int nc = warpN * 64 + ni * 8 + g;
                b[ni][0] = __float_as_uint(Bs[cb][kk + tig][nc]);
                b[ni][1] = __float_as_uint(Bs[cb][kk + tig + 4][nc]);
            }
#pragma unroll
            for (int mi = 0; mi < 2; mi++)
#pragma unroll
                for (int ni = 0; ni < 8; ni++)
                    mma_tf32(acc[mi][ni], a[mi], b[ni]);
        }
        __syncthreads();
    }

    float ps[2][2][2] = {}, pd[2][2][2] = {};
#pragma unroll
    for (int mi = 0; mi < 2; mi++) {
        int row0 = bm + warpM * 32 + mi * 16 + g;
        int row1 = row0 + 8;
#pragma unroll
        for (int ni = 0; ni < 8; ni++) {
            int col = bn + warpN * 64 + ni * 8 + tig * 2;
            int hh = ni >> 2;
            float s0 = __ldg(&as1[col]), s1 = __ldg(&as1[col + 1]);
            float d0 = __ldg(&ad1[col]), d1 = __ldg(&ad1[col + 1]);
            float c0 = acc[mi][ni][0], c1 = acc[mi][ni][1];
            float c2 = acc[mi][ni][2], c3 = acc[mi][ni][3];
            ps[mi][0][hh] += c0 * s0 + c1 * s1;
            ps[mi][1][hh] += c2 * s0 + c3 * s1;
            pd[mi][0][hh] += c0 * d0 + c1 * d1;
            pd[mi][1][hh] += c2 * d0 + c3 * d1;
            if (row0 < NN) g_h1b[(row0 * HC + col) >> 1] = __floats2bfloat162_rn(c0, c1);
            if (row1 < NN) g_h1b[(row1 * HC + col) >> 1] = __floats2bfloat162_rn(c2, c3);
        }
    }
#pragma unroll
    for (int mi = 0; mi < 2; mi++)
#pragma unroll
        for (int rh = 0; rh < 2; rh++)
#pragma unroll
            for (int hh = 0; hh < 2; hh++) {
                float vs = ps[mi][rh][hh], vd = pd[mi][rh][hh];
                vs += __shfl_xor_sync(0xffffffffu, vs, 1);
                vs += __shfl_xor_sync(0xffffffffu, vs, 2);
                vd += __shfl_xor_sync(0xffffffffu, vd, 1);
                vd += __shfl_xor_sync(0xffffffffu, vd, 2);
                if (tig == 0) {
                    int row = bm + warpM * 32 + mi * 16 + g + rh * 8;
                    int head = ((bn + warpN * 64) >> 5) + hh;
                    if (row < NN) {
                        g_asrc1[row * HH + head] = vs;
                        g_adst1[row * HH + head] = vd;
                    }
                }
            }
}

// ---------------- layer-1: single-pass agg + fused bias/relu store (round-10)
__global__ void k_l1agg(const float* __restrict__ b1v) {
    int tid = threadIdx.x;
    int node = blockIdx.x * 2 + (tid >> 7);
    int w = (tid >> 5) & 3, lane = tid & 31;
    int row = g_rowptr[node], end = g_rowptr[node + 1];
    int q = lane >> 3, cr = lane & 7;
    float dh = g_adst1[node * HH + cr];          // head = cr for exp phase
    int hsel = 2 * w + (cr >> 2);                // head of this lane's channels
    int ub = w * 32 + cr * 4;                    // bf16x2 unit base within row
    float acc[8] = {};
    float psum = 0.f;
    for (int k = row; k < end; k += 8) {
        int i0 = k + q, i1 = k + 4 + q;
        bool e0 = i0 < end, e1 = i1 < end;
        int s0 = g_csr_src[e0 ? i0 : end - 1];
        int s1 = g_csr_src[e1 ? i1 : end - 1];
        float p0 = e0 ? __expf(lrelu(__ldg(&g_asrc1[s0 * HH + cr]) + dh)) : 0.f;
        float p1 = e1 ? __expf(lrelu(__ldg(&g_asrc1[s1 * HH + cr]) + dh)) : 0.f;
        psum += p0 + p1;
        float w0 = __shfl_sync(0xffffffffu, p0, (q << 3) + hsel);
        float w1 = __shfl_sync(0xffffffffu, p1, (q << 3) + hsel);
        uint4 u0 = make_uint4(0u, 0u, 0u, 0u), u1 = make_uint4(0u, 0u, 0u, 0u);
        if (e0) u0 = __ldg((const uint4*)&g_h1b[s0 * (HC / 2) + ub]);
        if (e1) u1 = __ldg((const uint4*)&g_h1b[s1 * (HC / 2) + ub]);
        {
            float2 f0 = __bfloat1622float2(*reinterpret_cast<__nv_bfloat162*>(&u0.x));
            float2 f1 = __bfloat1622float2(*reinterpret_cast<__nv_bfloat162*>(&u0.y));
            float2 f2 = __bfloat1622float2(*reinterpret_cast<__nv_bfloat162*>(&u0.z));
            float2 f3 = __bfloat1622float2(*reinterpret_cast<__nv_bfloat162*>(&u0.w));
            acc[0] += w0 * f0.x; acc[1] += w0 * f0.y;
            acc[2] += w0 * f1.x; acc[3] += w0 * f1.y;
            acc[4] += w0 * f2.x; acc[5] += w0 * f2.y;
            acc[6] += w0 * f3.x; acc[7] += w0 * f3.y;
        }
        {
            float2 f0 = __bfloat1622float2(*reinterpret_cast<__nv_bfloat162*>(&u1.x));
            float2 f1 = __bfloat1622float2(*reinterpret_cast<__nv_bfloat162*>(&u1.y));
            float2 f2 = __bfloat1622float2(*reinterpret_cast<__nv_bfloat162*>(&u1.z));
            float2 f3 = __bfloat1622float2(*reinterpret_cast<__nv_bfloat162*>(&u1.w));
            acc[0] += w1 * f0.x; acc[1] += w1 * f0.y;
            acc[2] += w1 * f1.x; acc[3] += w1 * f1.y;
            acc[4] += w1 * f2.x; acc[5] += w1 * f2.y;
            acc[6] += w1 * f3.x; acc[7] += w1 * f3.y;
        }
    }
#pragma unroll
    for (int i = 0; i < 8; i++) {
        acc[i] += __shfl_xor_sync(0xffffffffu, acc[i], 8);
        acc[i] += __shfl_xor_sync(0xffffffffu, acc[i], 16);
    }
    psum += __shfl_xor_sync(0xffffffffu, psum, 8);
    psum += __shfl_xor_sync(0xffffffffu, psum, 16);
    float inv = 1.f / __shfl_sync(0xffffffffu, psum, hsel);
    if (lane < 8) {
        int cb = ub * 2;                          // float channel base
        float4 bA = *(const float4*)&b1v[cb];
        float4 bB = *(const float4*)&b1v[cb + 4];
        __half2 h0 = __floats2half2_rn(fmaxf(acc[0] * inv + bA.x, 0.f), fmaxf(acc[1] * inv + bA.y, 0.f));
        __half2 h1 = __floats2half2_rn(fmaxf(acc[2] * inv + bA.z, 0.f), fmaxf(acc[3] * inv + bA.w, 0.f));
        __half2 h2 = __floats2half2_rn(fmaxf(acc[4] * inv + bB.x, 0.f), fmaxf(acc[5] * inv + bB.y, 0.f));
        __half2 h3 = __floats2half2_rn(fmaxf(acc[6] * inv + bB.z, 0.f), fmaxf(acc[7] * inv + bB.w, 0.f));
        uint4 st = make_uint4(*(unsigned*)&h0, *(unsigned*)&h1,
                              *(unsigned*)&h2, *(unsigned*)&h3);
        *(uint4*)&g_out1h[node * (HC / 2) + ub] = st;
    }
}

// ---------------- GEMM2 (fp16 TC, cp.async 2-stage): g2 = out1 @ W2 ----------
__global__ void k_gemm2_tc(const float* __restrict__ W2,
                           const float* __restrict__ as2v, const float* __restrict__ ad2v) {
    __shared__ unsigned Ah[2][128][20];   // half2; 16 used + 4 pad
    __shared__ unsigned Bp[2][16][40];    // half2 packed along k
    int tid = threadIdx.x;
    int wid = tid >> 5, lane = tid & 31;
    int g = lane >> 2, tig = lane & 3;
    int bm = blockIdx.x * 128;

    float acc[5][4] = {};

    int ar = tid >> 1, ac4 = (tid & 1) * 2;
    int arow = bm + ar; if (arow > NN - 1) arow = NN - 1;

    for (int it = 0; it < 9; it++) {
        if (it < 8) {
            int k0 = it * 32, buf = it & 1;
            CP_ASYNC16((unsigned)__cvta_generic_to_shared(&Ah[buf][ar][ac4 * 4]),
                       &g_out1h[arow * (HC / 2) + (k0 >> 1) + ac4 * 4]);
            CP_ASYNC16((unsigned)__cvta_generic_to_shared(&Ah[buf][ar][(ac4 + 1) * 4]),
                       &g_out1h[arow * (HC / 2) + (k0 >> 1) + (ac4 + 1) * 4]);
            CP_COMMIT();
            for (int idx = tid; idx < 640; idx += 256) {
                int k2 = idx / 40, n = idx - k2 * 40;
                float f0 = W2[(k0 + 2 * k2) * OUTC + n];
                float f1 = W2[(k0 + 2 * k2 + 1) * OUTC + n];
                __half2 hp = __floats2half2_rn(f0, f1);
                Bp[buf][k2][n] = *(unsigned*)&hp;
            }
        }
        if (it == 0) continue;
        if (it < 8) CP_WAIT1(); else CP_WAIT0();
        __syncthreads();
        int cb = (it - 1) & 1;
        int mrow = wid * 16;
#pragma unroll
        for (int s = 0; s < 2; s++) {
            unsigned a[4];
            a[0] = Ah[cb][mrow + g][8 * s + tig];
            a[1] = Ah[cb][mrow + g + 8][8 * s + tig];
            a[2] = Ah[cb][mrow + g][8 * s + tig + 4];
            a[3] = Ah[cb][mrow + g + 8][8 * s + tig + 4];
#pragma unroll
            for (int ni = 0; ni < 5; ni++) {
                unsigned b[2];
                int nc = ni * 8 + g;
                b[0] = Bp[cb][8 * s + tig][nc];
                b[1] = Bp[cb][8 * s + tig + 4][nc];
                mma_f16(acc[ni], a, b);
            }
        }
        __syncthreads();
    }

    int row0 = bm + wid * 16 + g;
    int row1 = row0 + 8;
    float ps0 = 0.f, ps1 = 0.f, pd0 = 0.f, pd1 = 0.f;
#pragma unroll
    for (int ni = 0; ni < 5; ni++) {
        int col = ni * 8 + tig * 2;
        float s0 = __ldg(&as2v[col]), s1 = __ldg(&as2v[col + 1]);
        float d0 = __ldg(&ad2v[col]), d1 = __ldg(&ad2v[col + 1]);
        float c0 = acc[ni][0], c1 = acc[ni][1], c2 = acc[ni][2], c3 = acc[ni][3];
        ps0 += c0 * s0 + c1 * s1;
        ps1 += c2 * s0 + c3 * s1;
        pd0 += c0 * d0 + c1 * d1;
        pd1 += c2 * d0 + c3 * d1;
        if (row0 < NN) g_g2h[row0 * (OUTC / 2) + (col >> 1)] = __floats2half2_rn(c0, c1);
        if (row1 < NN) g_g2h[row1 * (OUTC / 2) + (col >> 1)] = __floats2half2_rn(c2, c3);
    }
    ps0 += __shfl_xor_sync(0xffffffffu, ps0, 1); ps0 += __shfl_xor_sync(0xffffffffu, ps0, 2);
    ps1 += __shfl_xor_sync(0xffffffffu, ps1, 1); ps1 += __shfl_xor_sync(0xffffffffu, ps1, 2);
    pd0 += __shfl_xor_sync(0xffffffffu, pd0, 1); pd0 += __shfl_xor_sync(0xffffffffu, pd0, 2);
    pd1 += __shfl_xor_sync(0xffffffffu, pd1, 1); pd1 += __shfl_xor_sync(0xffffffffu, pd1, 2);
    if (tig == 0) {
        if (row0 < NN) { g_as2[row0] = ps0; g_ad2[row0] = pd0; }
        if (row1 < NN) { g_as2[row1] = ps1; g_ad2[row1] = pd1; }
    }
}

// ---------------- layer-2: vectorized single-pass agg + bias + log_softmax ---
// Warp per node. 6 edges in flight: lane = (q, r) = (lane/5, lane%5).
// Lanes 0-5 compute exp once per edge; gather lanes read one LDG.128 = 8 of 40
// channels of edge q. Cross-q shuffle reduce, then lanes 0-4 do log_softmax.
__global__ void k_l2agg(float* __restrict__ dout, const float* __restrict__ b2) {
    int node = (blockIdx.x * blockDim.x + threadIdx.x) >> 5;
    int lane = threadIdx.x & 31;
    if (node >= NN) return;
    int row = g_rowptr[node], end = g_rowptr[node + 1];
    float adi = g_ad2[node];
    int q = lane / 5, r = lane - 5 * q;          // q 0..6 (lane30:6, lane31:6/r1)
    bool gat = lane < 30;
    int qq = gat ? q : 0;
    float acc[8] = {};
    float psum = 0.f;                             // partial on lanes 0..5
    for (int k = row; k < end; k += 6) {
        int srcL = 0; float p = 0.f;
        if (lane < 6) {
            int idx = k + lane;
            bool e = idx < end;
            srcL = g_csr_src[e ? idx : end - 1];
            p = e ? __expf(lrelu(__ldg(&g_as2[srcL]) + adi)) : 0.f;
            psum += p;
        }
        int sq = __shfl_sync(0xffffffffu, srcL, qq);
        float pq = __shfl_sync(0xffffffffu, p, qq);
        uint4 u = make_uint4(0u, 0u, 0u, 0u);
        if (gat && (k + q < end))
            u = __ldg((const uint4*)&g_g2h[sq * (OUTC / 2) + r * 4]);
        float2 f0 = __half22float2(*reinterpret_cast<__half2*>(&u.x));
        float2 f1 = __half22float2(*reinterpret_cast<__half2*>(&u.y));
        float2 f2 = __half22float2(*reinterpret_cast<__half2*>(&u.z));
        float2 f3 = __half22float2(*reinterpret_cast<__half2*>(&u.w));
        acc[0] += pq * f0.x; acc[1] += pq * f0.y;
        acc[2] += pq * f1.x; acc[3] += pq * f1.y;
        acc[4] += pq * f2.x; acc[5] += pq * f2.y;
        acc[6] += pq * f3.x; acc[7] += pq * f3.y;
    }
    // total psum (lanes 0..5 hold partials; others hold 0)
    float tp = 0.f;
#pragma unroll
    for (int j = 0; j < 6; j++) tp += __shfl_sync(0xffffffffu, psum, j);
    float inv = 1.f / tp;
    // channel totals: sum acc over the 6 q-groups at fixed r
    float tot[8];
#pragma unroll
    for (int j = 0; j < 8; j++) {
        float s = 0.f;
#pragma unroll
        for (int g6 = 0; g6 < 6; g6++)
            s += __shfl_sync(0xffffffffu, acc[j], g6 * 5 + r);
        tot[j] = s;
    }
    // lanes 0..4 (q==0) own channels lane*8 .. lane*8+7
    bool act = lane < 5;
    float v[8];
#pragma unroll
    for (int j = 0; j < 8; j++) {
        float bj = act ? b2[lane * 8 + j] : 0.f;
        v[j] = act ? (tot[j] * inv + bj) : -3.4e38f;
    }
    float mx = v[0];
#pragma unroll
    for (int j = 1; j < 8; j++) mx = fmaxf(mx, v[j]);
#pragma unroll
    for (int m = 4; m >= 1; m >>= 1)
        mx = fmaxf(mx, __shfl_xor_sync(0xffffffffu, mx, m));
    float se = 0.f;
    if (act) {
#pragma unroll
        for (int j = 0; j < 8; j++) se += expf(v[j] - mx);
    }
#pragma unroll
    for (int m = 4; m >= 1; m >>= 1)
        se += __shfl_xor_sync(0xffffffffu, se, m);
    float ls = logf(se);
    if (act) {
        float4 o0 = make_float4(v[0] - mx - ls, v[1] - mx - ls, v[2] - mx - ls, v[3] - mx - ls);
        float4 o1 = make_float4(v[4] - mx - ls, v[5] - mx - ls, v[6] - mx - ls, v[7] - mx - ls);
        *(float4*)&dout[node * OUTC + lane * 8] = o0;
        *(float4*)&dout[node * OUTC + lane * 8 + 4] = o1;
    }
}

// ---------------- launch (two parallel branches in the captured graph) -------
extern "C" void kernel_launch(void* const* d_in, const int* in_sizes, int n_in,
                              void* d_out, int out_size) {
    const float* x   = (const float*)d_in[0];
    const int*   ei  = (const int*)d_in[1];
    const float* W1  = (const float*)d_in[2];
    const float* as1 = (const float*)d_in[3];
    const float* ad1 = (const float*)d_in[4];
    const float* b1  = (const float*)d_in[5];
    const float* W2  = (const float*)d_in[6];
    const float* as2 = (const float*)d_in[7];
    const float* ad2 = (const float*)d_in[8];
    const float* b2  = (const float*)d_in[9];
    float* out = (float*)d_out;

    static cudaStream_t s1 = 0;
    static cudaEvent_t evF = 0, evJ = 0;
    if (s1 == 0) {
        cudaStreamCreateWithFlags(&s1, cudaStreamNonBlocking);
        cudaEventCreateWithFlags(&evF, cudaEventDisableTiming);
        cudaEventCreateWithFlags(&evJ, cudaEventDisableTiming);
    }

    // fork: gemm1 (reads x/W1 only) parallel to CSR build
    cudaEventRecord(evF, (cudaStream_t)0);
    cudaStreamWaitEvent(s1, evF, 0);
    k_gemm1_tc<<<dim3((NN + 127) / 128, HC / 128), 256, 0, s1>>>(x, W1, as1, ad1);
    cudaEventRecord(evJ, s1);

    // CSR build on the main stream
    k_hist<<<(EE / 4 + 255) / 256, 256>>>(ei);
    k_scan_f<<<NBLK, SCAN_BLK>>>();
    k_scatter<<<(ETOT + 255) / 256, 256>>>(ei);

    // join, then dependent chain
    cudaStreamWaitEvent((cudaStream_t)0, evJ, 0);
    k_l1agg<<<NN / 2, 256>>>(b1);
    k_gemm2_tc<<<(NN + 127) / 128, 256>>>(W2, as2, ad2);
    k_l2agg<<<(NN + 7) / 8, 256>>>(out, b2);
}

// round 13
// speedup vs baseline: 1.1320x; 1.0420x over previous
#include <cuda_runtime.h>
#include <cuda_bf16.h>
#include <cuda_fp16.h>

#define NN   50000
#define EE   800000
#define ETOT 850000      // EE + NN self loops
#define INC  128
#define HH   8
#define HC   256
#define OUTC 40
#define NEG  0.2f
#define SCAN_BLK 1024
#define NBLK ((NN + SCAN_BLK - 1) / SCAN_BLK)   // 49

// ---------------- scratch (device globals; no allocation) ----------------
__device__ __nv_bfloat162 g_h1b[NN * HC / 2];   // layer-1 features (bf16 pairs)
__device__ float  g_asrc1[NN * HH];
__device__ float  g_adst1[NN * HH];
__device__ __half2 g_out1h[NN * HC / 2];        // relu(out1+b1) (fp16 pairs) = layer-2 input
__device__ __half2 g_g2h[NN * OUTC / 2];        // layer-2 features (fp16 pairs)
__device__ float  g_as2[NN];
__device__ float  g_ad2[NN];
__device__ int    g_deg[NN];                    // REAL edges only (self loop added in scan)
__device__ int    g_bagg[NBLK];                 // published block aggregates (+1), 0 = not ready
__device__ int    g_rowptr[NN + 1];
__device__ int    g_cursor[NN];
__device__ int    g_csr_src[ETOT];

__device__ __forceinline__ float lrelu(float x) { return x > 0.f ? x : NEG * x; }

__device__ __forceinline__ void mma_tf32(float* c, const unsigned* a, const unsigned* b) {
    asm("mma.sync.aligned.m16n8k8.row.col.f32.tf32.tf32.f32 "
        "{%0,%1,%2,%3},{%4,%5,%6,%7},{%8,%9},{%0,%1,%2,%3};"
        : "+f"(c[0]), "+f"(c[1]), "+f"(c[2]), "+f"(c[3])
        : "r"(a[0]), "r"(a[1]), "r"(a[2]), "r"(a[3]), "r"(b[0]), "r"(b[1]));
}

__device__ __forceinline__ void mma_f16(float* c, const unsigned* a, const unsigned* b) {
    asm("mma.sync.aligned.m16n8k16.row.col.f32.f16.f16.f32 "
        "{%0,%1,%2,%3},{%4,%5,%6,%7},{%8,%9},{%0,%1,%2,%3};"
        : "+f"(c[0]), "+f"(c[1]), "+f"(c[2]), "+f"(c[3])
        : "r"(a[0]), "r"(a[1]), "r"(a[2]), "r"(a[3]), "r"(b[0]), "r"(b[1]));
}

#define CP_ASYNC16(sa, ga) asm volatile("cp.async.cg.shared.global [%0],[%1],16;\n" :: "r"(sa), "l"(ga))
#define CP_COMMIT()  asm volatile("cp.async.commit_group;\n" ::: "memory")
#define CP_WAIT1()   asm volatile("cp.async.wait_group 1;\n" ::: "memory")
#define CP_WAIT0()   asm volatile("cp.async.wait_group 0;\n" ::: "memory")

// ---------------- CSR build ----------------
__global__ void k_hist(const int* __restrict__ ei) {
    int t = blockIdx.x * blockDim.x + threadIdx.x;
    if (t * 4 >= EE) return;
    int4 d = *(const int4*)&ei[EE + t * 4];
    atomicAdd(&g_deg[d.x], 1);
    atomicAdd(&g_deg[d.y], 1);
    atomicAdd(&g_deg[d.z], 1);
    atomicAdd(&g_deg[d.w], 1);
}

// single-kernel exclusive scan with decoupled lookback (49 blocks, all resident)
__global__ void k_scan_f() {
    __shared__ int wsum[32];
    __shared__ int sbase;
    int t = threadIdx.x, b = blockIdx.x;
    int lane = t & 31, wid = t >> 5;
    int i = b * SCAN_BLK + t;
    int v = (i < NN) ? g_deg[i] + 1 : 0;      // +1 self loop
    int sc = v;
#pragma unroll
    for (int off = 1; off < 32; off <<= 1) {
        int u = __shfl_up_sync(0xffffffffu, sc, off);
        if (lane >= off) sc += u;
    }
    if (lane == 31) wsum[wid] = sc;
    __syncthreads();
    if (t < 32) {
        int u = wsum[t];
#pragma unroll
        for (int off = 1; off < 32; off <<= 1) {
            int uu = __shfl_up_sync(0xffffffffu, u, off);
            if (t >= off) u += uu;
        }
        wsum[t] = u;
        if (t == 31) atomicExch(&g_bagg[b], u + 1);   // publish total (+1 flag)
    }
    __syncthreads();
    if (t < 32) {
        int base = 0;
        for (int j = lane; j < b; j += 32) {
            int a;
            do { a = atomicAdd(&g_bagg[j], 0); } while (a == 0);
            base += a - 1;
        }
#pragma unroll
        for (int m = 16; m >= 1; m >>= 1) base += __shfl_xor_sync(0xffffffffu, base, m);
        if (t == 0) sbase = base;
    }
    __syncthreads();
    int warpoff = (wid > 0) ? wsum[wid - 1] : 0;
    if (i < NN) {
        int pos = sbase + warpoff + sc - v;    // exclusive
        g_rowptr[i] = pos;
        g_cursor[i] = pos;
    }
    if (b == 0 && t == 0) g_rowptr[NN] = ETOT;
}

// vectorized scatter: 4 edges per thread (int4 loads, 4 atomics in flight)
__global__ void k_scatter(const int* __restrict__ ei) {
    int t = blockIdx.x * blockDim.x + threadIdx.x;
    int e = t * 4;
    if (e < EE) {
        int4 s = *(const int4*)&ei[e];
        int4 d = *(const int4*)&ei[EE + e];
        int p0 = atomicAdd(&g_cursor[d.x], 1);
        int p1 = atomicAdd(&g_cursor[d.y], 1);
        int p2 = atomicAdd(&g_cursor[d.z], 1);
        int p3 = atomicAdd(&g_cursor[d.w], 1);
        g_csr_src[p0] = s.x;
        g_csr_src[p1] = s.y;
        g_csr_src[p2] = s.z;
        g_csr_src[p3] = s.w;
    }
    int sl = t - EE / 4;                        // self loops
    if (sl >= 0 && sl < NN) {
        int pos = atomicAdd(&g_cursor[sl], 1);
        g_csr_src[pos] = sl;
    }
    if (t < NN) g_deg[t] = 0;     // re-zero for next call (deterministic)
    if (t < NBLK) g_bagg[t] = 0;  // re-arm lookback flags
}

// ---------------- GEMM1 (tf32 TC, cp.async double-buffered) + fused att coeffs
__global__ void k_gemm1_tc(const float* __restrict__ A, const float* __restrict__ B,
                           const float* __restrict__ as1, const float* __restrict__ ad1) {
    __shared__ float As[2][128][20];
    __shared__ float Bs[2][16][132];
    int tid = threadIdx.x;
    int wid = tid >> 5, lane = tid & 31;
    int warpM = wid & 3, warpN = wid >> 2;
    int g = lane >> 2, tig = lane & 3;
    int bm = blockIdx.x * 128, bn = blockIdx.y * 128;

    float acc[2][8][4] = {};

    int ar = tid >> 2, ac = (tid & 3) * 4;
    int arow0 = bm + ar;       if (arow0 > NN - 1) arow0 = NN - 1;
    int arow1 = bm + ar + 64;  if (arow1 > NN - 1) arow1 = NN - 1;
    int br = tid >> 5, bc = (tid & 31) * 4;

    for (int it = 0; it < 9; it++) {
        if (it < 8) {
            int k0 = it * 16, buf = it & 1;
            CP_ASYNC16((unsigned)__cvta_generic_to_shared(&As[buf][ar][ac]),      &A[arow0 * INC + k0 + ac]);
            CP_ASYNC16((unsigned)__cvta_generic_to_shared(&As[buf][ar + 64][ac]), &A[arow1 * INC + k0 + ac]);
            CP_ASYNC16((unsigned)__cvta_generic_to_shared(&Bs[buf][br][bc]),      &B[(k0 + br) * HC + bn + bc]);
            CP_ASYNC16((unsigned)__cvta_generic_to_shared(&Bs[buf][br + 8][bc]),  &B[(k0 + br + 8) * HC + bn + bc]);
            CP_COMMIT();
        }
        if (it == 0) continue;
        if (it < 8) CP_WAIT1(); else CP_WAIT0();
        __syncthreads();
        int cb = (it - 1) & 1;
#pragma unroll
        for (int kk = 0; kk < 16; kk += 8) {
            unsigned a[2][4];
#pragma unroll
            for (int mi = 0; mi < 2; mi++) {
                int mrow = warpM * 32 + mi * 16;
                a[mi][0] = __float_as_uint(As[cb][mrow + g][kk + tig]);
                a[mi][1] = __float_as_uint(As[cb][mrow + g + 8][kk + tig]);
                a[mi][2] = __float_as_uint(As[cb][mrow + g][kk + tig + 4]);
                a[mi][3] = __float_as_uint(As[cb][mrow + g + 8][kk + tig + 4]);
            }
            unsigned b[8][2];
#pragma unroll
            for (int ni = 0; ni < 8; ni++) {
                int nc = warpN * 64 + ni * 8 + g;
                b[ni][0] = __float_as_uint(Bs[cb][kk + tig][nc]);
                b[ni][1] = __float_as_uint(Bs[cb][kk + tig + 4][nc]);
            }
#pragma unroll
            for (int mi = 0; mi < 2; mi++)
#pragma unroll
                for (int ni = 0; ni < 8; ni++)
                    mma_tf32(acc[mi][ni], a[mi], b[ni]);
        }
        __syncthreads();
    }

    float ps[2][2][2] = {}, pd[2][2][2] = {};
#pragma unroll
    for (int mi = 0; mi < 2; mi++) {
        int row0 = bm + warpM * 32 + mi * 16 + g;
        int row1 = row0 + 8;
#pragma unroll
        for (int ni = 0; ni < 8; ni++) {
            int col = bn + warpN * 64 + ni * 8 + tig * 2;
            int hh = ni >> 2;
            float s0 = __ldg(&as1[col]), s1 = __ldg(&as1[col + 1]);
            float d0 = __ldg(&ad1[col]), d1 = __ldg(&ad1[col + 1]);
            float c0 = acc[mi][ni][0], c1 = acc[mi][ni][1];
            float c2 = acc[mi][ni][2], c3 = acc[mi][ni][3];
            ps[mi][0][hh] += c0 * s0 + c1 * s1;
            ps[mi][1][hh] += c2 * s0 + c3 * s1;
            pd[mi][0][hh] += c0 * d0 + c1 * d1;
            pd[mi][1][hh] += c2 * d0 + c3 * d1;
            if (row0 < NN) g_h1b[(row0 * HC + col) >> 1] = __floats2bfloat162_rn(c0, c1);
            if (row1 < NN) g_h1b[(row1 * HC + col) >> 1] = __floats2bfloat162_rn(c2, c3);
        }
    }
#pragma unroll
    for (int mi = 0; mi < 2; mi++)
#pragma unroll
        for (int rh = 0; rh < 2; rh++)
#pragma unroll
            for (int hh = 0; hh < 2; hh++) {
                float vs = ps[mi][rh][hh], vd = pd[mi][rh][hh];
                vs += __shfl_xor_sync(0xffffffffu, vs, 1);
                vs += __shfl_xor_sync(0xffffffffu, vs, 2);
                vd += __shfl_xor_sync(0xffffffffu, vd, 1);
                vd += __shfl_xor_sync(0xffffffffu, vd, 2);
                if (tig == 0) {
                    int row = bm + warpM * 32 + mi * 16 + g + rh * 8;
                    int head = ((bn + warpN * 64) >> 5) + hh;
                    if (row < NN) {
                        g_asrc1[row * HH + head] = vs;
                        g_adst1[row * HH + head] = vd;
                    }
                }
            }
}

// ---------------- layer-1: single-pass agg + fused bias/relu store -----------
__global__ void k_l1agg(const float* __restrict__ b1v) {
    int tid = threadIdx.x;
    int node = blockIdx.x * 2 + (tid >> 7);
    int w = (tid >> 5) & 3, lane = tid & 31;
    int row = g_rowptr[node], end = g_rowptr[node + 1];
    int q = lane >> 3, cr = lane & 7;
    float dh = g_adst1[node * HH + cr];          // head = cr for exp phase
    int hsel = 2 * w + (cr >> 2);                // head of this lane's channels
    int ub = w * 32 + cr * 4;                    // bf16x2 unit base within row
    float acc[8] = {};
    float psum = 0.f;
    for (int k = row; k < end; k += 8) {
        int i0 = k + q, i1 = k + 4 + q;
        bool e0 = i0 < end, e1 = i1 < end;
        int s0 = g_csr_src[e0 ? i0 : end - 1];
        int s1 = g_csr_src[e1 ? i1 : end - 1];
        float p0 = e0 ? __expf(lrelu(__ldg(&g_asrc1[s0 * HH + cr]) + dh)) : 0.f;
        float p1 = e1 ? __expf(lrelu(__ldg(&g_asrc1[s1 * HH + cr]) + dh)) : 0.f;
        psum += p0 + p1;
        float w0 = __shfl_sync(0xffffffffu, p0, (q << 3) + hsel);
        float w1 = __shfl_sync(0xffffffffu, p1, (q << 3) + hsel);
        uint4 u0 = make_uint4(0u, 0u, 0u, 0u), u1 = make_uint4(0u, 0u, 0u, 0u);
        if (e0) u0 = __ldg((const uint4*)&g_h1b[s0 * (HC / 2) + ub]);
        if (e1) u1 = __ldg((const uint4*)&g_h1b[s1 * (HC / 2) + ub]);
        {
            float2 f0 = __bfloat1622float2(*reinterpret_cast<__nv_bfloat162*>(&u0.x));
            float2 f1 = __bfloat1622float2(*reinterpret_cast<__nv_bfloat162*>(&u0.y));
            float2 f2 = __bfloat1622float2(*reinterpret_cast<__nv_bfloat162*>(&u0.z));
            float2 f3 = __bfloat1622float2(*reinterpret_cast<__nv_bfloat162*>(&u0.w));
            acc[0] += w0 * f0.x; acc[1] += w0 * f0.y;
            acc[2] += w0 * f1.x; acc[3] += w0 * f1.y;
            acc[4] += w0 * f2.x; acc[5] += w0 * f2.y;
            acc[6] += w0 * f3.x; acc[7] += w0 * f3.y;
        }
        {
            float2 f0 = __bfloat1622float2(*reinterpret_cast<__nv_bfloat162*>(&u1.x));
            float2 f1 = __bfloat1622float2(*reinterpret_cast<__nv_bfloat162*>(&u1.y));
            float2 f2 = __bfloat1622float2(*reinterpret_cast<__nv_bfloat162*>(&u1.z));
            float2 f3 = __bfloat1622float2(*reinterpret_cast<__nv_bfloat162*>(&u1.w));
            acc[0] += w1 * f0.x; acc[1] += w1 * f0.y;
            acc[2] += w1 * f1.x; acc[3] += w1 * f1.y;
            acc[4] += w1 * f2.x; acc[5] += w1 * f2.y;
            acc[6] += w1 * f3.x; acc[7] += w1 * f3.y;
        }
    }
#pragma unroll
    for (int i = 0; i < 8; i++) {
        acc[i] += __shfl_xor_sync(0xffffffffu, acc[i], 8);
        acc[i] += __shfl_xor_sync(0xffffffffu, acc[i], 16);
    }
    psum += __shfl_xor_sync(0xffffffffu, psum, 8);
    psum += __shfl_xor_sync(0xffffffffu, psum, 16);
    float inv = 1.f / __shfl_sync(0xffffffffu, psum, hsel);
    if (lane < 8) {
        int cb = ub * 2;                          // float channel base
        float4 bA = *(const float4*)&b1v[cb];
        float4 bB = *(const float4*)&b1v[cb + 4];
        __half2 h0 = __floats2half2_rn(fmaxf(acc[0] * inv + bA.x, 0.f), fmaxf(acc[1] * inv + bA.y, 0.f));
        __half2 h1 = __floats2half2_rn(fmaxf(acc[2] * inv + bA.z, 0.f), fmaxf(acc[3] * inv + bA.w, 0.f));
        __half2 h2 = __floats2half2_rn(fmaxf(acc[4] * inv + bB.x, 0.f), fmaxf(acc[5] * inv + bB.y, 0.f));
        __half2 h3 = __floats2half2_rn(fmaxf(acc[6] * inv + bB.z, 0.f), fmaxf(acc[7] * inv + bB.w, 0.f));
        uint4 st = make_uint4(*(unsigned*)&h0, *(unsigned*)&h1,
                              *(unsigned*)&h2, *(unsigned*)&h3);
        *(uint4*)&g_out1h[node * (HC / 2) + ub] = st;
    }
}

// ---------------- GEMM2 (fp16 TC, cp.async 2-stage): g2 = out1 @ W2 ----------
__global__ void k_gemm2_tc(const float* __restrict__ W2,
                           const float* __restrict__ as2v, const float* __restrict__ ad2v) {
    __shared__ unsigned Ah[2][128][20];   // half2; 16 used + 4 pad
    __shared__ unsigned Bp[2][16][40];    // half2 packed along k
    int tid = threadIdx.x;
    int wid = tid >> 5, lane = tid & 31;
    int g = lane >> 2, tig = lane & 3;
    int bm = blockIdx.x * 128;

    float acc[5][4] = {};

    int ar = tid >> 1, ac4 = (tid & 1) * 2;
    int arow = bm + ar; if (arow > NN - 1) arow = NN - 1;

    for (int it = 0; it < 9; it++) {
        if (it < 8) {
            int k0 = it * 32, buf = it & 1;
            CP_ASYNC16((unsigned)__cvta_generic_to_shared(&Ah[buf][ar][ac4 * 4]),
                       &g_out1h[arow * (HC / 2) + (k0 >> 1) + ac4 * 4]);
            CP_ASYNC16((unsigned)__cvta_generic_to_shared(&Ah[buf][ar][(ac4 + 1) * 4]),
                       &g_out1h[arow * (HC / 2) + (k0 >> 1) + (ac4 + 1) * 4]);
            CP_COMMIT();
            for (int idx = tid; idx < 640; idx += 256) {
                int k2 = idx / 40, n = idx - k2 * 40;
                float f0 = W2[(k0 + 2 * k2) * OUTC + n];
                float f1 = W2[(k0 + 2 * k2 + 1) * OUTC + n];
                __half2 hp = __floats2half2_rn(f0, f1);
                Bp[buf][k2][n] = *(unsigned*)&hp;
            }
        }
        if (it == 0) continue;
        if (it < 8) CP_WAIT1(); else CP_WAIT0();
        __syncthreads();
        int cb = (it - 1) & 1;
        int mrow = wid * 16;
#pragma unroll
        for (int s = 0; s < 2; s++) {
            unsigned a[4];
            a[0] = Ah[cb][mrow + g][8 * s + tig];
            a[1] = Ah[cb][mrow + g + 8][8 * s + tig];
            a[2] = Ah[cb][mrow + g][8 * s + tig + 4];
            a[3] = Ah[cb][mrow + g + 8][8 * s + tig + 4];
#pragma unroll
            for (int ni = 0; ni < 5; ni++) {
                unsigned b[2];
                int nc = ni * 8 + g;
                b[0] = Bp[cb][8 * s + tig][nc];
                b[1] = Bp[cb][8 * s + tig + 4][nc];
                mma_f16(acc[ni], a, b);
            }
        }
        __syncthreads();
    }

    int row0 = bm + wid * 16 + g;
    int row1 = row0 + 8;
    float ps0 = 0.f, ps1 = 0.f, pd0 = 0.f, pd1 = 0.f;
#pragma unroll
    for (int ni = 0; ni < 5; ni++) {
        int col = ni * 8 + tig * 2;
        float s0 = __ldg(&as2v[col]), s1 = __ldg(&as2v[col + 1]);
        float d0 = __ldg(&ad2v[col]), d1 = __ldg(&ad2v[col + 1]);
        float c0 = acc[ni][0], c1 = acc[ni][1], c2 = acc[ni][2], c3 = acc[ni][3];
        ps0 += c0 * s0 + c1 * s1;
        ps1 += c2 * s0 + c3 * s1;
        pd0 += c0 * d0 + c1 * d1;
        pd1 += c2 * d0 + c3 * d1;
        if (row0 < NN) g_g2h[row0 * (OUTC / 2) + (col >> 1)] = __floats2half2_rn(c0, c1);
        if (row1 < NN) g_g2h[row1 * (OUTC / 2) + (col >> 1)] = __floats2half2_rn(c2, c3);
    }
    ps0 += __shfl_xor_sync(0xffffffffu, ps0, 1); ps0 += __shfl_xor_sync(0xffffffffu, ps0, 2);
    ps1 += __shfl_xor_sync(0xffffffffu, ps1, 1); ps1 += __shfl_xor_sync(0xffffffffu, ps1, 2);
    pd0 += __shfl_xor_sync(0xffffffffu, pd0, 1); pd0 += __shfl_xor_sync(0xffffffffu, pd0, 2);
    pd1 += __shfl_xor_sync(0xffffffffu, pd1, 1); pd1 += __shfl_xor_sync(0xffffffffu, pd1, 2);
    if (tig == 0) {
        if (row0 < NN) { g_as2[row0] = ps0; g_ad2[row0] = pd0; }
        if (row1 < NN) { g_as2[row1] = ps1; g_ad2[row1] = pd1; }
    }
}

// ---------------- layer-2: single-pass agg + bias + log_softmax (round-10) ---
__global__ void k_l2agg(float* __restrict__ dout, const float* __restrict__ b2) {
    int node = (blockIdx.x * blockDim.x + threadIdx.x) >> 5;
    int lane = threadIdx.x & 31;
    if (node >= NN) return;
    int row = g_rowptr[node], end = g_rowptr[node + 1];
    float adi = g_ad2[node];
    float a0 = 0.f, a1 = 0.f, psum = 0.f;
    for (int k = row; k < end; k += 32) {
        int idx = k + lane;
        int sl = g_csr_src[idx < end ? idx : end - 1];
        float p = (idx < end) ? __expf(lrelu(__ldg(&g_as2[sl]) + adi)) : 0.f;
        psum += p;
        int cnt = end - k; if (cnt > 32) cnt = 32;
        for (int e0 = 0; e0 < cnt; e0 += 8) {
#pragma unroll
            for (int e2 = 0; e2 < 8; e2++) {
                int e = e0 + e2;
                int s = __shfl_sync(0xffffffffu, sl, e);
                float al = __shfl_sync(0xffffffffu, p, e);
                unsigned u = 0;
                if (e < cnt && lane < 20) u = __ldg((const unsigned*)&g_g2h[s * (OUTC / 2) + lane]);
                __half2 hv = *reinterpret_cast<__half2*>(&u);
                float2 f = __half22float2(hv);
                a0 += al * f.x;
                a1 += al * f.y;
            }
        }
    }
#pragma unroll
    for (int m = 16; m >= 1; m >>= 1) psum += __shfl_xor_sync(0xffffffffu, psum, m);
    float inv = 1.f / psum;
    float v0 = -3.4e38f, v1 = -3.4e38f;
    if (lane < 20) {
        v0 = a0 * inv + b2[2 * lane];
        v1 = a1 * inv + b2[2 * lane + 1];
    }
    float mx = fmaxf(v0, v1);
#pragma unroll
    for (int m = 16; m >= 1; m >>= 1)
        mx = fmaxf(mx, __shfl_xor_sync(0xffffffffu, mx, m));
    float sum = (lane < 20) ? (expf(v0 - mx) + expf(v1 - mx)) : 0.f;
#pragma unroll
    for (int m = 16; m >= 1; m >>= 1)
        sum += __shfl_xor_sync(0xffffffffu, sum, m);
    float ls = logf(sum);
    if (lane < 20)
        *(float2*)&dout[node * OUTC + 2 * lane] = make_float2(v0 - mx - ls, v1 - mx - ls);
}

// ---------------- launch (two parallel branches in the captured graph) -------
extern "C" void kernel_launch(void* const* d_in, const int* in_sizes, int n_in,
                              void* d_out, int out_size) {
    const float* x   = (const float*)d_in[0];
    const int*   ei  = (const int*)d_in[1];
    const float* W1  = (const float*)d_in[2];
    const float* as1 = (const float*)d_in[3];
    const float* ad1 = (const float*)d_in[4];
    const float* b1  = (const float*)d_in[5];
    const float* W2  = (const float*)d_in[6];
    const float* as2 = (const float*)d_in[7];
    const float* ad2 = (const float*)d_in[8];
    const float* b2  = (const float*)d_in[9];
    float* out = (float*)d_out;

    static cudaStream_t s1 = 0;
    static cudaEvent_t evF = 0, evJ = 0;
    if (s1 == 0) {
        cudaStreamCreateWithFlags(&s1, cudaStreamNonBlocking);
        cudaEventCreateWithFlags(&evF, cudaEventDisableTiming);
        cudaEventCreateWithFlags(&evJ, cudaEventDisableTiming);
    }

    // fork: gemm1 (reads x/W1 only) parallel to CSR build
    cudaEventRecord(evF, (cudaStream_t)0);
    cudaStreamWaitEvent(s1, evF, 0);
    k_gemm1_tc<<<dim3((NN + 127) / 128, HC / 128), 256, 0, s1>>>(x, W1, as1, ad1);
    cudaEventRecord(evJ, s1);

    // CSR build on the main stream
    k_hist<<<(EE / 4 + 255) / 256, 256>>>(ei);
    k_scan_f<<<NBLK, SCAN_BLK>>>();
    k_scatter<<<(EE / 4 + NN + 255) / 256, 256>>>(ei);

    // join, then dependent chain
    cudaStreamWaitEvent((cudaStream_t)0, evJ, 0);
    k_l1agg<<<NN / 2, 256>>>(b1);
    k_gemm2_tc<<<(NN + 127) / 128, 256>>>(W2, as2, ad2);
    k_l2agg<<<(NN + 7) / 8, 256>>>(out, b2);
}

// round 14
// speedup vs baseline: 1.3451x; 1.1883x over previous
#include <cuda_runtime.h>
#include <cuda_bf16.h>
#include <cuda_fp16.h>

#define NN   50000
#define EE   800000
#define ETOT 850000      // EE + NN self loops
#define INC  128
#define HH   8
#define HC   256
#define OUTC 40
#define NEG  0.2f
#define SCAN_BLK 1024
#define NBLK ((NN + SCAN_BLK - 1) / SCAN_BLK)   // 49

// ---------------- scratch (device globals; no allocation) ----------------
__device__ __nv_bfloat162 g_h1b[NN * HC / 2];   // layer-1 features (bf16 pairs)
__device__ float  g_asrc1[NN * HH];
__device__ float  g_adst1[NN * HH];
__device__ __half2 g_out1h[NN * HC / 2];        // relu(out1+b1) (fp16 pairs) = layer-2 input
__device__ __half2 g_g2h[NN * OUTC / 2];        // layer-2 features (fp16 pairs)
__device__ float  g_as2[NN];
__device__ float  g_ad2[NN];
__device__ int    g_deg[NN];                    // REAL edges only (self loop added in scan)
__device__ int    g_bagg[NBLK];                 // published block aggregates (+1), 0 = not ready
__device__ int    g_rowptr[NN + 1];
__device__ int    g_cursor[NN];
__device__ int    g_csr_src[ETOT];

__device__ __forceinline__ float lrelu(float x) { return x > 0.f ? x : NEG * x; }

__device__ __forceinline__ void mma_tf32(float* c, const unsigned* a, const unsigned* b) {
    asm("mma.sync.aligned.m16n8k8.row.col.f32.tf32.tf32.f32 "
        "{%0,%1,%2,%3},{%4,%5,%6,%7},{%8,%9},{%0,%1,%2,%3};"
        : "+f"(c[0]), "+f"(c[1]), "+f"(c[2]), "+f"(c[3])
        : "r"(a[0]), "r"(a[1]), "r"(a[2]), "r"(a[3]), "r"(b[0]), "r"(b[1]));
}

__device__ __forceinline__ void mma_f16(float* c, const unsigned* a, const unsigned* b) {
    asm("mma.sync.aligned.m16n8k16.row.col.f32.f16.f16.f32 "
        "{%0,%1,%2,%3},{%4,%5,%6,%7},{%8,%9},{%0,%1,%2,%3};"
        : "+f"(c[0]), "+f"(c[1]), "+f"(c[2]), "+f"(c[3])
        : "r"(a[0]), "r"(a[1]), "r"(a[2]), "r"(a[3]), "r"(b[0]), "r"(b[1]));
}

#define CP_ASYNC16(sa, ga) asm volatile("cp.async.cg.shared.global [%0],[%1],16;\n" :: "r"(sa), "l"(ga))
#define CP_COMMIT()  asm volatile("cp.async.commit_group;\n" ::: "memory")
#define CP_WAIT1()   asm volatile("cp.async.wait_group 1;\n" ::: "memory")
#define CP_WAIT0()   asm volatile("cp.async.wait_group 0;\n" ::: "memory")

// ---------------- CSR build ----------------
__global__ void k_hist(const int* __restrict__ ei) {
    int t = blockIdx.x * blockDim.x + threadIdx.x;
    if (t * 4 >= EE) return;
    int4 d = *(const int4*)&ei[EE + t * 4];
    atomicAdd(&g_deg[d.x], 1);
    atomicAdd(&g_deg[d.y], 1);
    atomicAdd(&g_deg[d.z], 1);
    atomicAdd(&g_deg[d.w], 1);
}

// single-kernel exclusive scan with decoupled lookback (49 blocks, all resident)
__global__ void k_scan_f() {
    __shared__ int wsum[32];
    __shared__ int sbase;
    int t = threadIdx.x, b = blockIdx.x;
    int lane = t & 31, wid = t >> 5;
    int i = b * SCAN_BLK + t;
    int v = (i < NN) ? g_deg[i] + 1 : 0;      // +1 self loop
    int sc = v;
#pragma unroll
    for (int off = 1; off < 32; off <<= 1) {
        int u = __shfl_up_sync(0xffffffffu, sc, off);
        if (lane >= off) sc += u;
    }
    if (lane == 31) wsum[wid] = sc;
    __syncthreads();
    if (t < 32) {
        int u = wsum[t];
#pragma unroll
        for (int off = 1; off < 32; off <<= 1) {
            int uu = __shfl_up_sync(0xffffffffu, u, off);
            if (t >= off) u += uu;
        }
        wsum[t] = u;
        if (t == 31) atomicExch(&g_bagg[b], u + 1);   // publish total (+1 flag)
    }
    __syncthreads();
    if (t < 32) {
        int base = 0;
        for (int j = lane; j < b; j += 32) {
            int a;
            do { a = atomicAdd(&g_bagg[j], 0); } while (a == 0);
            base += a - 1;
        }
#pragma unroll
        for (int m = 16; m >= 1; m >>= 1) base += __shfl_xor_sync(0xffffffffu, base, m);
        if (t == 0) sbase = base;
    }
    __syncthreads();
    int warpoff = (wid > 0) ? wsum[wid - 1] : 0;
    if (i < NN) {
        int pos = sbase + warpoff + sc - v;    // exclusive
        g_rowptr[i] = pos;
        g_cursor[i] = pos;
    }
    if (b == 0 && t == 0) g_rowptr[NN] = ETOT;
}

__global__ void k_scatter(const int* __restrict__ ei) {
    int e = blockIdx.x * blockDim.x + threadIdx.x;
    if (e < ETOT) {
        int src, dst;
        if (e < EE) { src = ei[e]; dst = ei[EE + e]; }
        else        { src = e - EE; dst = src; }
        int pos = atomicAdd(&g_cursor[dst], 1);
        g_csr_src[pos] = src;
    }
    if (e < NN) g_deg[e] = 0;     // re-zero for next call (deterministic)
    if (e < NBLK) g_bagg[e] = 0;  // re-arm lookback flags
}

// ---------------- GEMM1 (tf32 TC, cp.async double-buffered) + fused att coeffs
__global__ void k_gemm1_tc(const float* __restrict__ A, const float* __restrict__ B,
                           const float* __restrict__ as1, const float* __restrict__ ad1) {
    __shared__ float As[2][128][20];
    __shared__ float Bs[2][16][132];
    int tid = threadIdx.x;
    int wid = tid >> 5, lane = tid & 31;
    int warpM = wid & 3, warpN = wid >> 2;
    int g = lane >> 2, tig = lane & 3;
    int bm = blockIdx.x * 128, bn = blockIdx.y * 128;

    float acc[2][8][4] = {};

    int ar = tid >> 2, ac = (tid & 3) * 4;
    int arow0 = bm + ar;       if (arow0 > NN - 1) arow0 = NN - 1;
    int arow1 = bm + ar + 64;  if (arow1 > NN - 1) arow1 = NN - 1;
    int br = tid >> 5, bc = (tid & 31) * 4;

    for (int it = 0; it < 9; it++) {
        if (it < 8) {
            int k0 = it * 16, buf = it & 1;
            CP_ASYNC16((unsigned)__cvta_generic_to_shared(&As[buf][ar][ac]),      &A[arow0 * INC + k0 + ac]);
            CP_ASYNC16((unsigned)__cvta_generic_to_shared(&As[buf][ar + 64][ac]), &A[arow1 * INC + k0 + ac]);
            CP_ASYNC16((unsigned)__cvta_generic_to_shared(&Bs[buf][br][bc]),      &B[(k0 + br) * HC + bn + bc]);
            CP_ASYNC16((unsigned)__cvta_generic_to_shared(&Bs[buf][br + 8][bc]),  &B[(k0 + br + 8) * HC + bn + bc]);
            CP_COMMIT();
        }
        if (it == 0) continue;
        if (it < 8) CP_WAIT1(); else CP_WAIT0();
        __syncthreads();
        int cb = (it - 1) & 1;
#pragma unroll
        for (int kk = 0; kk < 16; kk += 8) {
            unsigned a[2][4];
#pragma unroll
            for (int mi = 0; mi < 2; mi++) {
                int mrow = warpM * 32 + mi * 16;
                a[mi][0] = __float_as_uint(As[cb][mrow + g][kk + tig]);
                a[mi][1] = __float_as_uint(As[cb][mrow + g + 8][kk + tig]);
                a[mi][2] = __float_as_uint(As[cb][mrow + g][kk + tig + 4]);
                a[mi][3] = __float_as_uint(As[cb][mrow + g + 8][kk + tig + 4]);
            }
            unsigned b[8][2];
#pragma unroll
            for (int ni = 0; ni < 8; ni++) {
                int nc = warpN * 64 + ni * 8 + g;
                b[ni][0] = __float_as_uint(Bs[cb][kk + tig][nc]);
                b[ni][1] = __float_as_uint(Bs[cb][kk + tig + 4][nc]);
            }
#pragma unroll
            for (int mi = 0; mi < 2; mi++)
#pragma unroll
                for (int ni = 0; ni < 8; ni++)
                    mma_tf32(acc[mi][ni], a[mi], b[ni]);
        }
        __syncthreads();
    }

    float ps[2][2][2] = {}, pd[2][2][2] = {};
#pragma unroll
    for (int mi = 0; mi < 2; mi++) {
        int row0 = bm + warpM * 32 + mi * 16 + g;
        int row1 = row0 + 8;
#pragma unroll
        for (int ni = 0; ni < 8; ni++) {
            int col = bn + warpN * 64 + ni * 8 + tig * 2;
            int hh = ni >> 2;
            float s0 = __ldg(&as1[col]), s1 = __ldg(&as1[col + 1]);
            float d0 = __ldg(&ad1[col]), d1 = __ldg(&ad1[col + 1]);
            float c0 = acc[mi][ni][0], c1 = acc[mi][ni][1];
            float c2 = acc[mi][ni][2], c3 = acc[mi][ni][3];
            ps[mi][0][hh] += c0 * s0 + c1 * s1;
            ps[mi][1][hh] += c2 * s0 + c3 * s1;
            pd[mi][0][hh] += c0 * d0 + c1 * d1;
            pd[mi][1][hh] += c2 * d0 + c3 * d1;
            if (row0 < NN) g_h1b[(row0 * HC + col) >> 1] = __floats2bfloat162_rn(c0, c1);
            if (row1 < NN) g_h1b[(row1 * HC + col) >> 1] = __floats2bfloat162_rn(c2, c3);
        }
    }
#pragma unroll
    for (int mi = 0; mi < 2; mi++)
#pragma unroll
        for (int rh = 0; rh < 2; rh++)
#pragma unroll
            for (int hh = 0; hh < 2; hh++) {
                float vs = ps[mi][rh][hh], vd = pd[mi][rh][hh];
                vs += __shfl_xor_sync(0xffffffffu, vs, 1);
                vs += __shfl_xor_sync(0xffffffffu, vs, 2);
                vd += __shfl_xor_sync(0xffffffffu, vd, 1);
                vd += __shfl_xor_sync(0xffffffffu, vd, 2);
                if (tig == 0) {
                    int row = bm + warpM * 32 + mi * 16 + g + rh * 8;
                    int head = ((bn + warpN * 64) >> 5) + hh;
                    if (row < NN) {
                        g_asrc1[row * HH + head] = vs;
                        g_adst1[row * HH + head] = vd;
                    }
                }
            }
}

// ---------------- layer-1: warp-per-node, full-row LDG.128 gather ------------
// Lane owns channels lane*8..lane*8+7 (head = lane>>2). Exp phase: lane (q,h) =
// (lane>>3, lane&7) computes p for edge k+q, head h. 4 edges in flight.
__global__ void k_l1agg(const float* __restrict__ b1v) {
    int node = (blockIdx.x * blockDim.x + threadIdx.x) >> 5;
    int lane = threadIdx.x & 31;
    if (node >= NN) return;
    int row = g_rowptr[node], end = g_rowptr[node + 1];
    int q = lane >> 3, h = lane & 7;
    int hsel = lane >> 2;                        // head of this lane's channels
    float dh = g_adst1[node * HH + h];
    float acc[8] = {};
    float psum = 0.f;
    for (int k = row; k < end; k += 4) {
        int idx = k + q;
        bool ev = idx < end;
        int sq = g_csr_src[ev ? idx : end - 1];
        float p = ev ? __expf(lrelu(__ldg(&g_asrc1[sq * HH + h]) + dh)) : 0.f;
        psum += p;
#pragma unroll
        for (int e = 0; e < 4; e++) {
            int s = __shfl_sync(0xffffffffu, sq, e * 8);
            float we = __shfl_sync(0xffffffffu, p, e * 8 + hsel);
            uint4 u = make_uint4(0u, 0u, 0u, 0u);
            if (k + e < end) u = __ldg((const uint4*)&g_h1b[s * (HC / 2) + lane * 4]);
            float2 f0 = __bfloat1622float2(*reinterpret_cast<__nv_bfloat162*>(&u.x));
            float2 f1 = __bfloat1622float2(*reinterpret_cast<__nv_bfloat162*>(&u.y));
            float2 f2 = __bfloat1622float2(*reinterpret_cast<__nv_bfloat162*>(&u.z));
            float2 f3 = __bfloat1622float2(*reinterpret_cast<__nv_bfloat162*>(&u.w));
            acc[0] += we * f0.x; acc[1] += we * f0.y;
            acc[2] += we * f1.x; acc[3] += we * f1.y;
            acc[4] += we * f2.x; acc[5] += we * f2.y;
            acc[6] += we * f3.x; acc[7] += we * f3.y;
        }
    }
    // per-head sums live in lanes (·,h): reduce over edge-slot bits 3,4
    psum += __shfl_xor_sync(0xffffffffu, psum, 8);
    psum += __shfl_xor_sync(0xffffffffu, psum, 16);
    float inv = 1.f / __shfl_sync(0xffffffffu, psum, hsel);
    // bias + relu + fp16 store (8 channels per lane, one STG.128)
    float4 bA = *(const float4*)&b1v[lane * 8];
    float4 bB = *(const float4*)&b1v[lane * 8 + 4];
    __half2 h0 = __floats2half2_rn(fmaxf(acc[0] * inv + bA.x, 0.f), fmaxf(acc[1] * inv + bA.y, 0.f));
    __half2 h1 = __floats2half2_rn(fmaxf(acc[2] * inv + bA.z, 0.f), fmaxf(acc[3] * inv + bA.w, 0.f));
    __half2 h2 = __floats2half2_rn(fmaxf(acc[4] * inv + bB.x, 0.f), fmaxf(acc[5] * inv + bB.y, 0.f));
    __half2 h3 = __floats2half2_rn(fmaxf(acc[6] * inv + bB.z, 0.f), fmaxf(acc[7] * inv + bB.w, 0.f));
    uint4 st = make_uint4(*(unsigned*)&h0, *(unsigned*)&h1,
                          *(unsigned*)&h2, *(unsigned*)&h3);
    *(uint4*)&g_out1h[node * (HC / 2) + lane * 4] = st;
}

// ---------------- GEMM2 (fp16 TC, cp.async 2-stage): g2 = out1 @ W2 ----------
__global__ void k_gemm2_tc(const float* __restrict__ W2,
                           const float* __restrict__ as2v, const float* __restrict__ ad2v) {
    __shared__ unsigned Ah[2][128][20];   // half2; 16 used + 4 pad
    __shared__ unsigned Bp[2][16][40];    // half2 packed along k
    int tid = threadIdx.x;
    int wid = tid >> 5, lane = tid & 31;
    int g = lane >> 2, tig = lane & 3;
    int bm = blockIdx.x * 128;

    float acc[5][4] = {};

    int ar = tid >> 1, ac4 = (tid & 1) * 2;
    int arow = bm + ar; if (arow > NN - 1) arow = NN - 1;

    for (int it = 0; it < 9; it++) {
        if (it < 8) {
            int k0 = it * 32, buf = it & 1;
            CP_ASYNC16((unsigned)__cvta_generic_to_shared(&Ah[buf][ar][ac4 * 4]),
                       &g_out1h[arow * (HC / 2) + (k0 >> 1) + ac4 * 4]);
            CP_ASYNC16((unsigned)__cvta_generic_to_shared(&Ah[buf][ar][(ac4 + 1) * 4]),
                       &g_out1h[arow * (HC / 2) + (k0 >> 1) + (ac4 + 1) * 4]);
            CP_COMMIT();
            for (int idx = tid; idx < 640; idx += 256) {
                int k2 = idx / 40, n = idx - k2 * 40;
                float f0 = W2[(k0 + 2 * k2) * OUTC + n];
                float f1 = W2[(k0 + 2 * k2 + 1) * OUTC + n];
                __half2 hp = __floats2half2_rn(f0, f1);
                Bp[buf][k2][n] = *(unsigned*)&hp;
            }
        }
        if (it == 0) continue;
        if (it < 8) CP_WAIT1(); else CP_WAIT0();
        __syncthreads();
        int cb = (it - 1) & 1;
        int mrow = wid * 16;
#pragma unroll
        for (int s = 0; s < 2; s++) {
            unsigned a[4];
            a[0] = Ah[cb][mrow + g][8 * s + tig];
            a[1] = Ah[cb][mrow + g + 8][8 * s + tig];
            a[2] = Ah[cb][mrow + g][8 * s + tig + 4];
            a[3] = Ah[cb][mrow + g + 8][8 * s + tig + 4];
#pragma unroll
            for (int ni = 0; ni < 5; ni++) {
                unsigned b[2];
                int nc = ni * 8 + g;
                b[0] = Bp[cb][8 * s + tig][nc];
                b[1] = Bp[cb][8 * s + tig + 4][nc];
                mma_f16(acc[ni], a, b);
            }
        }
        __syncthreads();
    }

    int row0 = bm + wid * 16 + g;
    int row1 = row0 + 8;
    float ps0 = 0.f, ps1 = 0.f, pd0 = 0.f, pd1 = 0.f;
#pragma unroll
    for (int ni = 0; ni < 5; ni++) {
        int col = ni * 8 + tig * 2;
        float s0 = __ldg(&as2v[col]), s1 = __ldg(&as2v[col + 1]);
        float d0 = __ldg(&ad2v[col]), d1 = __ldg(&ad2v[col + 1]);
        float c0 = acc[ni][0], c1 = acc[ni][1], c2 = acc[ni][2], c3 = acc[ni][3];
        ps0 += c0 * s0 + c1 * s1;
        ps1 += c2 * s0 + c3 * s1;
        pd0 += c0 * d0 + c1 * d1;
        pd1 += c2 * d0 + c3 * d1;
        if (row0 < NN) g_g2h[row0 * (OUTC / 2) + (col >> 1)] = __floats2half2_rn(c0, c1);
        if (row1 < NN) g_g2h[row1 * (OUTC / 2) + (col >> 1)] = __floats2half2_rn(c2, c3);
    }
    ps0 += __shfl_xor_sync(0xffffffffu, ps0, 1); ps0 += __shfl_xor_sync(0xffffffffu, ps0, 2);
    ps1 += __shfl_xor_sync(0xffffffffu, ps1, 1); ps1 += __shfl_xor_sync(0xffffffffu, ps1, 2);
    pd0 += __shfl_xor_sync(0xffffffffu, pd0, 1); pd0 += __shfl_xor_sync(0xffffffffu, pd0, 2);
    pd1 += __shfl_xor_sync(0xffffffffu, pd1, 1); pd1 += __shfl_xor_sync(0xffffffffu, pd1, 2);
    if (tig == 0) {
        if (row0 < NN) { g_as2[row0] = ps0; g_ad2[row0] = pd0; }
        if (row1 < NN) { g_as2[row1] = ps1; g_ad2[row1] = pd1; }
    }
}

// ---------------- layer-2: single-pass agg + bias + log_softmax --------------
__global__ void k_l2agg(float* __restrict__ dout, const float* __restrict__ b2) {
    int node = (blockIdx.x * blockDim.x + threadIdx.x) >> 5;
    int lane = threadIdx.x & 31;
    if (node >= NN) return;
    int row = g_rowptr[node], end = g_rowptr[node + 1];
    float adi = g_ad2[node];
    float a0 = 0.f, a1 = 0.f, psum = 0.f;
    for (int k = row; k < end; k += 32) {
        int idx = k + lane;
        int sl = g_csr_src[idx < end ? idx : end - 1];
        float p = (idx < end) ? __expf(lrelu(__ldg(&g_as2[sl]) + adi)) : 0.f;
        psum += p;
        int cnt = end - k; if (cnt > 32) cnt = 32;
        for (int e0 = 0; e0 < cnt; e0 += 8) {
#pragma unroll
            for (int e2 = 0; e2 < 8; e2++) {
                int e = e0 + e2;
                int s = __shfl_sync(0xffffffffu, sl, e);
                float al = __shfl_sync(0xffffffffu, p, e);
                unsigned u = 0;
                if (e < cnt && lane < 20) u = __ldg((const unsigned*)&g_g2h[s * (OUTC / 2) + lane]);
                __half2 hv = *reinterpret_cast<__half2*>(&u);
                float2 f = __half22float2(hv);
                a0 += al * f.x;
                a1 += al * f.y;
            }
        }
    }
#pragma unroll
    for (int m = 16; m >= 1; m >>= 1) psum += __shfl_xor_sync(0xffffffffu, psum, m);
    float inv = 1.f / psum;
    float v0 = -3.4e38f, v1 = -3.4e38f;
    if (lane < 20) {
        v0 = a0 * inv + b2[2 * lane];
        v1 = a1 * inv + b2[2 * lane + 1];
    }
    float mx = fmaxf(v0, v1);
#pragma unroll
    for (int m = 16; m >= 1; m >>= 1)
        mx = fmaxf(mx, __shfl_xor_sync(0xffffffffu, mx, m));
    float sum = (lane < 20) ? (expf(v0 - mx) + expf(v1 - mx)) : 0.f;
#pragma unroll
    for (int m = 16; m >= 1; m >>= 1)
        sum += __shfl_xor_sync(0xffffffffu, sum, m);
    float ls = logf(sum);
    if (lane < 20)
        *(float2*)&dout[node * OUTC + 2 * lane] = make_float2(v0 - mx - ls, v1 - mx - ls);
}

// ---------------- launch (two parallel branches in the captured graph) -------
extern "C" void kernel_launch(void* const* d_in, const int* in_sizes, int n_in,
                              void* d_out, int out_size) {
    const float* x   = (const float*)d_in[0];
    const int*   ei  = (const int*)d_in[1];
    const float* W1  = (const float*)d_in[2];
    const float* as1 = (const float*)d_in[3];
    const float* ad1 = (const float*)d_in[4];
    const float* b1  = (const float*)d_in[5];
    const float* W2  = (const float*)d_in[6];
    const float* as2 = (const float*)d_in[7];
    const float* ad2 = (const float*)d_in[8];
    const float* b2  = (const float*)d_in[9];
    float* out = (float*)d_out;

    static cudaStream_t s1 = 0;
    static cudaEvent_t evF = 0, evJ = 0;
    if (s1 == 0) {
        cudaStreamCreateWithFlags(&s1, cudaStreamNonBlocking);
        cudaEventCreateWithFlags(&evF, cudaEventDisableTiming);
        cudaEventCreateWithFlags(&evJ, cudaEventDisableTiming);
    }

    // fork: gemm1 (reads x/W1 only) parallel to CSR build
    cudaEventRecord(evF, (cudaStream_t)0);
    cudaStreamWaitEvent(s1, evF, 0);
    k_gemm1_tc<<<dim3((NN + 127) / 128, HC / 128), 256, 0, s1>>>(x, W1, as1, ad1);
    cudaEventRecord(evJ, s1);

    // CSR build on the main stream
    k_hist<<<(EE / 4 + 255) / 256, 256>>>(ei);
    k_scan_f<<<NBLK, SCAN_BLK>>>();
    k_scatter<<<(ETOT + 255) / 256, 256>>>(ei);

    // join, then dependent chain
    cudaStreamWaitEvent((cudaStream_t)0, evJ, 0);
    k_l1agg<<<(NN + 7) / 8, 256>>>(b1);
    k_gemm2_tc<<<(NN + 127) / 128, 256>>>(W2, as2, ad2);
    k_l2agg<<<(NN + 7) / 8, 256>>>(out, b2);
}